// round 1
// baseline (speedup 1.0000x reference)
#include <cuda_runtime.h>
#include <cuda_bf16.h>

#define B_   16
#define N_   1029
#define H_   16
#define HD_  64
#define D_   1024
#define M_TOT (B_ * N_)     // 16464
#define PREFIX_ 5           // N - 1024
#define SCALE_ 0.125f       // HD^-0.5

// ---------------- scratch (allocation-free: device globals) ----------------
__device__ float g_P[(size_t)M_TOT * D_];             // projection temp [M, D]
__device__ float g_Q[(size_t)B_ * H_ * N_ * HD_];     // [B,H,N,HD]
__device__ float g_K[(size_t)B_ * H_ * N_ * HD_];
__device__ float g_V[(size_t)B_ * H_ * N_ * HD_];
__device__ float g_C[(size_t)M_TOT * D_];             // attn context [M, D]

// ---------------- SGEMM: Y[M,1024] = X[M,1024] @ W[1024,1024]^T + b --------
__global__ __launch_bounds__(256, 2)
void sgemm_bias_kernel(const float* __restrict__ A,
                       const float* __restrict__ W,
                       const float* __restrict__ bias,
                       float* __restrict__ Y, int Mrows) {
    __shared__ float As[8][128];
    __shared__ float Bs[8][128];
    const int tid = threadIdx.x;
    const int bm = blockIdx.y * 128;
    const int bn = blockIdx.x * 128;
    const int lr = tid >> 1;        // 0..127 load row
    const int lk = (tid & 1) * 4;   // 0 or 4
    const int tm = (tid >> 4) * 8;  // 0..120
    const int tn = (tid & 15) * 8;

    float acc[8][8];
#pragma unroll
    for (int i = 0; i < 8; i++)
#pragma unroll
        for (int j = 0; j < 8; j++) acc[i][j] = 0.f;

    const int arow = bm + lr;
    const bool av = arow < Mrows;
    const float* Ap = A + (size_t)(av ? arow : 0) * D_;
    const float* Wp = W + (size_t)(bn + lr) * D_;

    for (int k0 = 0; k0 < D_; k0 += 8) {
        float4 a4 = av ? *(const float4*)(Ap + k0 + lk) : make_float4(0, 0, 0, 0);
        float4 w4 = *(const float4*)(Wp + k0 + lk);
        As[lk + 0][lr] = a4.x; As[lk + 1][lr] = a4.y;
        As[lk + 2][lr] = a4.z; As[lk + 3][lr] = a4.w;
        Bs[lk + 0][lr] = w4.x; Bs[lk + 1][lr] = w4.y;
        Bs[lk + 2][lr] = w4.z; Bs[lk + 3][lr] = w4.w;
        __syncthreads();
#pragma unroll
        for (int k = 0; k < 8; k++) {
            float ar[8], br[8];
            float4 t0 = *(const float4*)&As[k][tm];
            float4 t1 = *(const float4*)&As[k][tm + 4];
            ar[0] = t0.x; ar[1] = t0.y; ar[2] = t0.z; ar[3] = t0.w;
            ar[4] = t1.x; ar[5] = t1.y; ar[6] = t1.z; ar[7] = t1.w;
            float4 u0 = *(const float4*)&Bs[k][tn];
            float4 u1 = *(const float4*)&Bs[k][tn + 4];
            br[0] = u0.x; br[1] = u0.y; br[2] = u0.z; br[3] = u0.w;
            br[4] = u1.x; br[5] = u1.y; br[6] = u1.z; br[7] = u1.w;
#pragma unroll
            for (int i = 0; i < 8; i++)
#pragma unroll
                for (int j = 0; j < 8; j++)
                    acc[i][j] = fmaf(ar[i], br[j], acc[i][j]);
        }
        __syncthreads();
    }

    float bb[8];
#pragma unroll
    for (int j = 0; j < 8; j++) bb[j] = bias[bn + tn + j];
#pragma unroll
    for (int i = 0; i < 8; i++) {
        int row = bm + tm + i;
        if (row < Mrows) {
            float* yp = Y + (size_t)row * D_ + bn + tn;
            float4 o0 = make_float4(acc[i][0] + bb[0], acc[i][1] + bb[1],
                                    acc[i][2] + bb[2], acc[i][3] + bb[3]);
            float4 o1 = make_float4(acc[i][4] + bb[4], acc[i][5] + bb[5],
                                    acc[i][6] + bb[6], acc[i][7] + bb[7]);
            *(float4*)(yp)     = o0;
            *(float4*)(yp + 4) = o1;
        }
    }
}

// ---------------- RoPE + [B,N,H,HD] -> [B,H,N,HD] transpose ---------------
__global__ void rope_transpose_kernel(const float* __restrict__ P,
                                      const float* __restrict__ sinp,
                                      const float* __restrict__ cosp,
                                      float* __restrict__ O,
                                      int apply_rope) {
    size_t i = (size_t)blockIdx.x * blockDim.x + threadIdx.x;
    const size_t total = (size_t)B_ * N_ * H_ * 32;
    if (i >= total) return;
    int d2 = (int)(i & 31);
    size_t r = i >> 5;
    int h = (int)(r % H_); r /= H_;
    int n = (int)(r % N_);
    int b = (int)(r / N_);

    const float* src = P + ((size_t)b * N_ + n) * D_ + h * HD_;
    float x1 = src[d2], x2 = src[d2 + 32];
    float y1 = x1, y2 = x2;
    if (apply_rope && n >= PREFIX_) {
        int p = n - PREFIX_;
        float c1 = cosp[p * HD_ + d2], c2 = cosp[p * HD_ + d2 + 32];
        float s1 = sinp[p * HD_ + d2], s2 = sinp[p * HD_ + d2 + 32];
        y1 = fmaf(x1, c1, -x2 * s1);   // x1*c1 - x2*s1
        y2 = fmaf(x2, c2,  x1 * s2);   // x2*c2 + x1*s2
    }
    float* dst = O + (((size_t)(b * H_ + h)) * N_ + n) * HD_;
    dst[d2] = y1;
    dst[d2 + 32] = y2;
}

// ---------------- Flash attention: 1 thread = 1 query row -----------------
__global__ __launch_bounds__(128)
void attn_kernel(const float* __restrict__ Q,
                 const float* __restrict__ K,
                 const float* __restrict__ V,
                 float* __restrict__ C) {
    __shared__ float Ksh[64 * 64];
    __shared__ float Vsh[64 * 64];
    const int tid = threadIdx.x;
    const int bh = blockIdx.y;
    const int b = bh / H_, h = bh % H_;
    const int n = blockIdx.x * 128 + tid;
    const bool valid = n < N_;
    const size_t base = (size_t)bh * N_ * HD_;

    float q[64];
    {
        const float* qp = Q + base + (size_t)(valid ? n : 0) * HD_;
#pragma unroll
        for (int d = 0; d < 64; d += 4) {
            float4 v4 = *(const float4*)(qp + d);
            q[d] = v4.x; q[d + 1] = v4.y; q[d + 2] = v4.z; q[d + 3] = v4.w;
        }
    }
    float o[64];
#pragma unroll
    for (int d = 0; d < 64; d++) o[d] = 0.f;
    float mrun = -1e30f, l = 0.f;

    for (int kt = 0; kt < N_; kt += 64) {
        const int cnt = min(64, N_ - kt);
        const float* kp = K + base + (size_t)kt * HD_;
        const float* vp = V + base + (size_t)kt * HD_;
        // cooperative tile load (coalesced float4)
        for (int i = tid; i < 64 * 64 / 4; i += 128) {
            float4 kv, vv;
            if (4 * i < cnt * 64) {
                kv = *(const float4*)(kp + 4 * i);
                vv = *(const float4*)(vp + 4 * i);
            } else {
                kv = make_float4(0, 0, 0, 0);
                vv = kv;
            }
            *(float4*)(Ksh + 4 * i) = kv;
            *(float4*)(Vsh + 4 * i) = vv;
        }
        __syncthreads();

        for (int j = 0; j < cnt; j++) {
            const float4* kr4 = (const float4*)(Ksh + j * 64);
            float s0 = 0.f, s1 = 0.f, s2 = 0.f, s3 = 0.f;
#pragma unroll
            for (int d4 = 0; d4 < 16; d4++) {
                float4 kk = kr4[d4];
                s0 = fmaf(q[4 * d4 + 0], kk.x, s0);
                s1 = fmaf(q[4 * d4 + 1], kk.y, s1);
                s2 = fmaf(q[4 * d4 + 2], kk.z, s2);
                s3 = fmaf(q[4 * d4 + 3], kk.w, s3);
            }
            float s = ((s0 + s1) + (s2 + s3)) * SCALE_;

            if (s > mrun) {
                float corr = __expf(mrun - s);
                l *= corr;
#pragma unroll
                for (int d = 0; d < 64; d++) o[d] *= corr;
                mrun = s;
            }
            float p = __expf(s - mrun);
            l += p;
            const float4* vr4 = (const float4*)(Vsh + j * 64);
#pragma unroll
            for (int d4 = 0; d4 < 16; d4++) {
                float4 vv = vr4[d4];
                o[4 * d4 + 0] = fmaf(p, vv.x, o[4 * d4 + 0]);
                o[4 * d4 + 1] = fmaf(p, vv.y, o[4 * d4 + 1]);
                o[4 * d4 + 2] = fmaf(p, vv.z, o[4 * d4 + 2]);
                o[4 * d4 + 3] = fmaf(p, vv.w, o[4 * d4 + 3]);
            }
        }
        __syncthreads();
    }

    if (valid) {
        float inv = 1.f / l;
        float* cp = C + ((size_t)(b * N_ + n)) * D_ + h * HD_;
#pragma unroll
        for (int d = 0; d < 64; d += 4) {
            float4 ov = make_float4(o[d] * inv, o[d + 1] * inv,
                                    o[d + 2] * inv, o[d + 3] * inv);
            *(float4*)(cp + d) = ov;
        }
    }
}

// --------------------------------- launcher --------------------------------
extern "C" void kernel_launch(void* const* d_in, const int* in_sizes, int n_in,
                              void* d_out, int out_size) {
    const float* hs = (const float*)d_in[0];
    const float* sn = (const float*)d_in[1];
    const float* cs = (const float*)d_in[2];
    const float* Wq = (const float*)d_in[3];
    const float* bq = (const float*)d_in[4];
    const float* Wk = (const float*)d_in[5];
    const float* bk = (const float*)d_in[6];
    const float* Wv = (const float*)d_in[7];
    const float* bv = (const float*)d_in[8];
    const float* Wo = (const float*)d_in[9];
    const float* bo = (const float*)d_in[10];
    float* out = (float*)d_out;

    float *P, *Qb, *Kb, *Vb, *Cb;
    cudaGetSymbolAddress((void**)&P,  g_P);
    cudaGetSymbolAddress((void**)&Qb, g_Q);
    cudaGetSymbolAddress((void**)&Kb, g_K);
    cudaGetSymbolAddress((void**)&Vb, g_V);
    cudaGetSymbolAddress((void**)&Cb, g_C);

    dim3 ggrid(D_ / 128, (M_TOT + 127) / 128);
    dim3 gblk(256);
    const size_t rope_total = (size_t)B_ * N_ * H_ * 32;
    dim3 rgrid((unsigned)((rope_total + 255) / 256)), rblk(256);
    dim3 agrid((N_ + 127) / 128, B_ * H_), ablk(128);

    sgemm_bias_kernel<<<ggrid, gblk>>>(hs, Wq, bq, P, M_TOT);
    rope_transpose_kernel<<<rgrid, rblk>>>(P, sn, cs, Qb, 1);
    sgemm_bias_kernel<<<ggrid, gblk>>>(hs, Wk, bk, P, M_TOT);
    rope_transpose_kernel<<<rgrid, rblk>>>(P, sn, cs, Kb, 1);
    sgemm_bias_kernel<<<ggrid, gblk>>>(hs, Wv, bv, P, M_TOT);
    rope_transpose_kernel<<<rgrid, rblk>>>(P, sn, cs, Vb, 0);
    attn_kernel<<<agrid, ablk>>>(Qb, Kb, Vb, Cb);
    sgemm_bias_kernel<<<ggrid, gblk>>>(Cb, Wo, bo, out, M_TOT);
}

// round 6
// speedup vs baseline: 1.6029x; 1.6029x over previous
#include <cuda_runtime.h>
#include <cuda_bf16.h>
#include <cstdint>

#define B_   16
#define N_   1029
#define H_   16
#define HD_  64
#define D_   1024
#define M_TOT (B_ * N_)     // 16464
#define PREFIX_ 5           // N - 1024
#define SCALE_ 0.125f       // HD^-0.5

// ---------------- scratch (allocation-free: device globals) ----------------
__device__ float g_P[(size_t)M_TOT * D_];             // projection temp [M, D]
__device__ float g_Q[(size_t)B_ * H_ * N_ * HD_];     // [B,H,N,HD]
__device__ float g_K[(size_t)B_ * H_ * N_ * HD_];
__device__ float g_V[(size_t)B_ * H_ * N_ * HD_];
__device__ float g_C[(size_t)M_TOT * D_];             // attn context [M, D]
__device__ __nv_bfloat16 g_Xhi[(size_t)M_TOT * D_];
__device__ __nv_bfloat16 g_Xlo[(size_t)M_TOT * D_];
__device__ __nv_bfloat16 g_Whi[(size_t)4 * D_ * D_];
__device__ __nv_bfloat16 g_Wlo[(size_t)4 * D_ * D_];

// ======================= PTX helpers (arch-agnostic) =======================
__device__ __forceinline__ uint32_t smem_u32(const void* p) {
    uint32_t a;
    asm("{ .reg .u64 t; cvta.to.shared.u64 t, %1; cvt.u32.u64 %0, t; }"
        : "=r"(a) : "l"(p));
    return a;
}
__device__ __forceinline__ void cp16(uint32_t dst, const void* src, int src_bytes) {
    asm volatile("cp.async.cg.shared.global [%0], [%1], 16, %2;"
                 :: "r"(dst), "l"(src), "r"(src_bytes));
}
#define CP_COMMIT() asm volatile("cp.async.commit_group;")
#define CP_WAIT1()  asm volatile("cp.async.wait_group 1;")
#define CP_WAIT0()  asm volatile("cp.async.wait_group 0;")

__device__ __forceinline__ void ldm4(uint32_t& r0, uint32_t& r1, uint32_t& r2,
                                     uint32_t& r3, uint32_t addr) {
    asm volatile("ldmatrix.sync.aligned.m8n8.x4.shared.b16 {%0,%1,%2,%3}, [%4];"
                 : "=r"(r0), "=r"(r1), "=r"(r2), "=r"(r3) : "r"(addr));
}
__device__ __forceinline__ void mma16816(float* c, const uint32_t* a,
                                         uint32_t b0, uint32_t b1) {
    asm volatile(
        "mma.sync.aligned.m16n8k16.row.col.f32.bf16.bf16.f32 "
        "{%0,%1,%2,%3}, {%4,%5,%6,%7}, {%8,%9}, {%0,%1,%2,%3};"
        : "+f"(c[0]), "+f"(c[1]), "+f"(c[2]), "+f"(c[3])
        : "r"(a[0]), "r"(a[1]), "r"(a[2]), "r"(a[3]), "r"(b0), "r"(b1));
}

// =============== fp32 -> (hi, lo) bf16 split conversion ====================
__global__ void f32_split_kernel(const float* __restrict__ x,
                                 __nv_bfloat16* __restrict__ hi,
                                 __nv_bfloat16* __restrict__ lo, int n4) {
    int i = blockIdx.x * blockDim.x + threadIdx.x;
    if (i >= n4) return;
    float4 v = ((const float4*)x)[i];
    __nv_bfloat16 h0 = __float2bfloat16(v.x), h1 = __float2bfloat16(v.y);
    __nv_bfloat16 h2 = __float2bfloat16(v.z), h3 = __float2bfloat16(v.w);
    __nv_bfloat16 l0 = __float2bfloat16(v.x - __bfloat162float(h0));
    __nv_bfloat16 l1 = __float2bfloat16(v.y - __bfloat162float(h1));
    __nv_bfloat16 l2 = __float2bfloat16(v.z - __bfloat162float(h2));
    __nv_bfloat16 l3 = __float2bfloat16(v.w - __bfloat162float(h3));
    ushort4 hh, ll;
    hh.x = *(unsigned short*)&h0; hh.y = *(unsigned short*)&h1;
    hh.z = *(unsigned short*)&h2; hh.w = *(unsigned short*)&h3;
    ll.x = *(unsigned short*)&l0; ll.y = *(unsigned short*)&l1;
    ll.z = *(unsigned short*)&l2; ll.w = *(unsigned short*)&l3;
    ((ushort4*)hi)[i] = hh;
    ((ushort4*)lo)[i] = ll;
}

// ========== warp-MMA split-bf16 GEMM: Y[M,1024] = X @ W^T + b =============
// CTA tile 128x128, 8 warps each 32x64. K chunks of 32, double-buffered.
// SMEM row stride 40 bf16 (80B) -> conflict-free ldmatrix.
#define KC        32
#define ASTRIDE   40
#define ARR_ELE   (128 * ASTRIDE)           // per array per stage (bf16)
#define ARR_B     (ARR_ELE * 2)             // 10240 bytes
#define STAGE_B   (4 * ARR_B)               // 40960 bytes
#define GSMEM     (2 * STAGE_B)             // 81920 bytes

__global__ __launch_bounds__(256, 1)
void gemm_mma_kernel(const __nv_bfloat16* __restrict__ Xhi,
                     const __nv_bfloat16* __restrict__ Xlo,
                     const __nv_bfloat16* __restrict__ Whi,
                     const __nv_bfloat16* __restrict__ Wlo,
                     const float* __restrict__ bias,
                     float* __restrict__ Y, int Mrows) {
    extern __shared__ __align__(16) char sm[];
    const uint32_t smb = smem_u32(sm);
    const int tid = threadIdx.x;
    const int wid = tid >> 5, lane = tid & 31;
    const int bm = blockIdx.y * 128;
    const int bn = blockIdx.x * 128;
    const int wm = (wid >> 1) * 32;          // warp M offset (0..96)
    const int wn = (wid & 1) * 64;           // warp N offset (0 / 64)

    // ---- loader indexing (per thread: 2 uint4 per array per stage) ----
    const int r0i = tid >> 2, kg0 = tid & 3;           // i = tid
    const int r1i = (tid + 256) >> 2, kg1 = tid & 3;   // i = tid+256
    const int ar0 = bm + r0i, ar1 = bm + r1i;
    const int p0 = (ar0 < Mrows) ? 16 : 0;
    const int p1 = (ar1 < Mrows) ? 16 : 0;
    const size_t ga0 = (size_t)(p0 ? ar0 : 0) * D_;
    const size_t ga1 = (size_t)(p1 ? ar1 : 0) * D_;
    const size_t gb0 = (size_t)(bn + r0i) * D_;
    const size_t gb1 = (size_t)(bn + r1i) * D_;
    const uint32_t so0 = (uint32_t)(r0i * ASTRIDE + kg0 * 8) * 2;
    const uint32_t so1 = (uint32_t)(r1i * ASTRIDE + kg1 * 8) * 2;

    // ---- ldmatrix address components ----
    const int li = lane & 7, ti = lane >> 3;
    int rowA[2], rowB[4];
#pragma unroll
    for (int mt = 0; mt < 2; mt++)
        rowA[mt] = (wm + mt * 16 + li + (ti & 1) * 8) * ASTRIDE + (ti >> 1) * 8;
#pragma unroll
    for (int np = 0; np < 4; np++)
        rowB[np] = (wn + np * 16 + li + (ti >> 1) * 8) * ASTRIDE + (ti & 1) * 8;

    float acc[2][8][4];
#pragma unroll
    for (int mt = 0; mt < 2; mt++)
#pragma unroll
        for (int nt = 0; nt < 8; nt++)
#pragma unroll
            for (int e = 0; e < 4; e++) acc[mt][nt][e] = 0.f;

    auto load_chunk = [&](int c) {
        const int kof = c * KC;
        const uint32_t st = smb + (c & 1) * STAGE_B;
        cp16(st + 0 * ARR_B + so0, Xhi + ga0 + kof + kg0 * 8, p0);
        cp16(st + 0 * ARR_B + so1, Xhi + ga1 + kof + kg1 * 8, p1);
        cp16(st + 1 * ARR_B + so0, Xlo + ga0 + kof + kg0 * 8, p0);
        cp16(st + 1 * ARR_B + so1, Xlo + ga1 + kof + kg1 * 8, p1);
        cp16(st + 2 * ARR_B + so0, Whi + gb0 + kof + kg0 * 8, 16);
        cp16(st + 2 * ARR_B + so1, Whi + gb1 + kof + kg1 * 8, 16);
        cp16(st + 3 * ARR_B + so0, Wlo + gb0 + kof + kg0 * 8, 16);
        cp16(st + 3 * ARR_B + so1, Wlo + gb1 + kof + kg1 * 8, 16);
        CP_COMMIT();
    };

    load_chunk(0);

    const int NCH = D_ / KC;  // 32
    for (int c = 0; c < NCH; c++) {
        if (c + 1 < NCH) { load_chunk(c + 1); CP_WAIT1(); }
        else            { CP_WAIT0(); }
        __syncthreads();

        const uint32_t st = smb + (c & 1) * STAGE_B;
#pragma unroll
        for (int k16 = 0; k16 < KC; k16 += 16) {
            uint32_t ahi[2][4], alo[2][4];
#pragma unroll
            for (int mt = 0; mt < 2; mt++) {
                uint32_t aad = st + 0 * ARR_B + (uint32_t)(rowA[mt] + k16) * 2;
                ldm4(ahi[mt][0], ahi[mt][1], ahi[mt][2], ahi[mt][3], aad);
                uint32_t lad = st + 1 * ARR_B + (uint32_t)(rowA[mt] + k16) * 2;
                ldm4(alo[mt][0], alo[mt][1], alo[mt][2], alo[mt][3], lad);
            }
#pragma unroll
            for (int np = 0; np < 4; np++) {
                uint32_t bh0, bh1, bh2, bh3, bl0, bl1, bl2, bl3;
                uint32_t bad = st + 2 * ARR_B + (uint32_t)(rowB[np] + k16) * 2;
                ldm4(bh0, bh1, bh2, bh3, bad);
                uint32_t bld = st + 3 * ARR_B + (uint32_t)(rowB[np] + k16) * 2;
                ldm4(bl0, bl1, bl2, bl3, bld);
#pragma unroll
                for (int mt = 0; mt < 2; mt++) {
                    mma16816(acc[mt][2 * np + 0], ahi[mt], bh0, bh1);
                    mma16816(acc[mt][2 * np + 1], ahi[mt], bh2, bh3);
                    mma16816(acc[mt][2 * np + 0], ahi[mt], bl0, bl1);
                    mma16816(acc[mt][2 * np + 1], ahi[mt], bl2, bl3);
                    mma16816(acc[mt][2 * np + 0], alo[mt], bh0, bh1);
                    mma16816(acc[mt][2 * np + 1], alo[mt], bh2, bh3);
                }
            }
        }
        __syncthreads();
    }

    // ---- epilogue: bias add + store ----
    const int cg = lane >> 2, tg = lane & 3;
#pragma unroll
    for (int mt = 0; mt < 2; mt++) {
        const int r0 = bm + wm + mt * 16 + cg;
        const int r1 = r0 + 8;
#pragma unroll
        for (int nt = 0; nt < 8; nt++) {
            const int col = bn + wn + nt * 8 + tg * 2;
            const float b0v = bias[col], b1v = bias[col + 1];
            if (r0 < Mrows) {
                float2 o = make_float2(acc[mt][nt][0] + b0v, acc[mt][nt][1] + b1v);
                *(float2*)(Y + (size_t)r0 * D_ + col) = o;
            }
            if (r1 < Mrows) {
                float2 o = make_float2(acc[mt][nt][2] + b0v, acc[mt][nt][3] + b1v);
                *(float2*)(Y + (size_t)r1 * D_ + col) = o;
            }
        }
    }
}

// ---------------- RoPE + [B,N,H,HD] -> [B,H,N,HD] transpose ---------------
__global__ void rope_transpose_kernel(const float* __restrict__ P,
                                      const float* __restrict__ sinp,
                                      const float* __restrict__ cosp,
                                      float* __restrict__ O,
                                      int apply_rope) {
    size_t i = (size_t)blockIdx.x * blockDim.x + threadIdx.x;
    const size_t total = (size_t)B_ * N_ * H_ * 32;
    if (i >= total) return;
    int d2 = (int)(i & 31);
    size_t r = i >> 5;
    int h = (int)(r % H_); r /= H_;
    int n = (int)(r % N_);
    int b = (int)(r / N_);

    const float* src = P + ((size_t)b * N_ + n) * D_ + h * HD_;
    float x1 = src[d2], x2 = src[d2 + 32];
    float y1 = x1, y2 = x2;
    if (apply_rope && n >= PREFIX_) {
        int p = n - PREFIX_;
        float c1 = cosp[p * HD_ + d2], c2 = cosp[p * HD_ + d2 + 32];
        float s1 = sinp[p * HD_ + d2], s2 = sinp[p * HD_ + d2 + 32];
        y1 = fmaf(x1, c1, -x2 * s1);
        y2 = fmaf(x2, c2,  x1 * s2);
    }
    float* dst = O + (((size_t)(b * H_ + h)) * N_ + n) * HD_;
    dst[d2] = y1;
    dst[d2 + 32] = y2;
}

// ---------------- Flash attention: 1 thread = 1 query row -----------------
__global__ __launch_bounds__(128)
void attn_kernel(const float* __restrict__ Q,
                 const float* __restrict__ K,
                 const float* __restrict__ V,
                 float* __restrict__ C) {
    __shared__ float Ksh[64 * 64];
    __shared__ float Vsh[64 * 64];
    const int tid = threadIdx.x;
    const int bh = blockIdx.y;
    const int b = bh / H_, h = bh % H_;
    const int n = blockIdx.x * 128 + tid;
    const bool valid = n < N_;
    const size_t base = (size_t)bh * N_ * HD_;

    float q[64];
    {
        const float* qp = Q + base + (size_t)(valid ? n : 0) * HD_;
#pragma unroll
        for (int d = 0; d < 64; d += 4) {
            float4 v4 = *(const float4*)(qp + d);
            q[d] = v4.x; q[d + 1] = v4.y; q[d + 2] = v4.z; q[d + 3] = v4.w;
        }
    }
    float o[64];
#pragma unroll
    for (int d = 0; d < 64; d++) o[d] = 0.f;
    float mrun = -1e30f, l = 0.f;

    for (int kt = 0; kt < N_; kt += 64) {
        const int cnt = min(64, N_ - kt);
        const float* kp = K + base + (size_t)kt * HD_;
        const float* vp = V + base + (size_t)kt * HD_;
        for (int i = tid; i < 64 * 64 / 4; i += 128) {
            float4 kv, vv;
            if (4 * i < cnt * 64) {
                kv = *(const float4*)(kp + 4 * i);
                vv = *(const float4*)(vp + 4 * i);
            } else {
                kv = make_float4(0, 0, 0, 0);
                vv = kv;
            }
            *(float4*)(Ksh + 4 * i) = kv;
            *(float4*)(Vsh + 4 * i) = vv;
        }
        __syncthreads();

        for (int j = 0; j < cnt; j++) {
            const float4* kr4 = (const float4*)(Ksh + j * 64);
            float s0 = 0.f, s1 = 0.f, s2 = 0.f, s3 = 0.f;
#pragma unroll
            for (int d4 = 0; d4 < 16; d4++) {
                float4 kk = kr4[d4];
                s0 = fmaf(q[4 * d4 + 0], kk.x, s0);
                s1 = fmaf(q[4 * d4 + 1], kk.y, s1);
                s2 = fmaf(q[4 * d4 + 2], kk.z, s2);
                s3 = fmaf(q[4 * d4 + 3], kk.w, s3);
            }
            float s = ((s0 + s1) + (s2 + s3)) * SCALE_;

            if (s > mrun) {
                float corr = __expf(mrun - s);
                l *= corr;
#pragma unroll
                for (int d = 0; d < 64; d++) o[d] *= corr;
                mrun = s;
            }
            float p = __expf(s - mrun);
            l += p;
            const float4* vr4 = (const float4*)(Vsh + j * 64);
#pragma unroll
            for (int d4 = 0; d4 < 16; d4++) {
                float4 vv = vr4[d4];
                o[4 * d4 + 0] = fmaf(p, vv.x, o[4 * d4 + 0]);
                o[4 * d4 + 1] = fmaf(p, vv.y, o[4 * d4 + 1]);
                o[4 * d4 + 2] = fmaf(p, vv.z, o[4 * d4 + 2]);
                o[4 * d4 + 3] = fmaf(p, vv.w, o[4 * d4 + 3]);
            }
        }
        __syncthreads();
    }

    if (valid) {
        float inv = 1.f / l;
        float* cp = C + ((size_t)(b * N_ + n)) * D_ + h * HD_;
#pragma unroll
        for (int d = 0; d < 64; d += 4) {
            float4 ov = make_float4(o[d] * inv, o[d + 1] * inv,
                                    o[d + 2] * inv, o[d + 3] * inv);
            *(float4*)(cp + d) = ov;
        }
    }
}

// --------------------------------- launcher --------------------------------
extern "C" void kernel_launch(void* const* d_in, const int* in_sizes, int n_in,
                              void* d_out, int out_size) {
    const float* hs = (const float*)d_in[0];
    const float* sn = (const float*)d_in[1];
    const float* cs = (const float*)d_in[2];
    const float* Wq = (const float*)d_in[3];
    const float* bq = (const float*)d_in[4];
    const float* Wk = (const float*)d_in[5];
    const float* bk = (const float*)d_in[6];
    const float* Wv = (const float*)d_in[7];
    const float* bv = (const float*)d_in[8];
    const float* Wo = (const float*)d_in[9];
    const float* bo = (const float*)d_in[10];
    float* out = (float*)d_out;

    float *P, *Qb, *Kb, *Vb, *Cb;
    __nv_bfloat16 *Xhi, *Xlo, *Whi, *Wlo;
    cudaGetSymbolAddress((void**)&P,   g_P);
    cudaGetSymbolAddress((void**)&Qb,  g_Q);
    cudaGetSymbolAddress((void**)&Kb,  g_K);
    cudaGetSymbolAddress((void**)&Vb,  g_V);
    cudaGetSymbolAddress((void**)&Cb,  g_C);
    cudaGetSymbolAddress((void**)&Xhi, g_Xhi);
    cudaGetSymbolAddress((void**)&Xlo, g_Xlo);
    cudaGetSymbolAddress((void**)&Whi, g_Whi);
    cudaGetSymbolAddress((void**)&Wlo, g_Wlo);

    cudaFuncSetAttribute(gemm_mma_kernel,
                         cudaFuncAttributeMaxDynamicSharedMemorySize, GSMEM);

    const int n4_hs = (M_TOT * D_) / 4;
    const int n4_w  = (D_ * D_) / 4;
    const size_t WN = (size_t)D_ * D_;

    dim3 cblk(256);
    dim3 cgrid_hs((n4_hs + 255) / 256), cgrid_w((n4_w + 255) / 256);
    dim3 ggrid(D_ / 128, (M_TOT + 127) / 128), gblk(256);
    const size_t rope_total = (size_t)B_ * N_ * H_ * 32;
    dim3 rgrid((unsigned)((rope_total + 255) / 256)), rblk(256);
    dim3 agrid((N_ + 127) / 128, B_ * H_), ablk(128);

    f32_split_kernel<<<cgrid_hs, cblk>>>(hs, Xhi, Xlo, n4_hs);
    f32_split_kernel<<<cgrid_w, cblk>>>(Wq, Whi + 0 * WN, Wlo + 0 * WN, n4_w);
    f32_split_kernel<<<cgrid_w, cblk>>>(Wk, Whi + 1 * WN, Wlo + 1 * WN, n4_w);
    f32_split_kernel<<<cgrid_w, cblk>>>(Wv, Whi + 2 * WN, Wlo + 2 * WN, n4_w);
    f32_split_kernel<<<cgrid_w, cblk>>>(Wo, Whi + 3 * WN, Wlo + 3 * WN, n4_w);

    gemm_mma_kernel<<<ggrid, gblk, GSMEM>>>(Xhi, Xlo, Whi + 0 * WN, Wlo + 0 * WN, bq, P, M_TOT);
    rope_transpose_kernel<<<rgrid, rblk>>>(P, sn, cs, Qb, 1);
    gemm_mma_kernel<<<ggrid, gblk, GSMEM>>>(Xhi, Xlo, Whi + 1 * WN, Wlo + 1 * WN, bk, P, M_TOT);
    rope_transpose_kernel<<<rgrid, rblk>>>(P, sn, cs, Kb, 1);
    gemm_mma_kernel<<<ggrid, gblk, GSMEM>>>(Xhi, Xlo, Whi + 2 * WN, Wlo + 2 * WN, bv, P, M_TOT);
    rope_transpose_kernel<<<rgrid, rblk>>>(P, sn, cs, Vb, 0);

    attn_kernel<<<agrid, ablk>>>(Qb, Kb, Vb, Cb);

    f32_split_kernel<<<cgrid_hs, cblk>>>(Cb, Xhi, Xlo, n4_hs);
    gemm_mma_kernel<<<ggrid, gblk, GSMEM>>>(Xhi, Xlo, Whi + 3 * WN, Wlo + 3 * WN, bo, out, M_TOT);
}

// round 10
// speedup vs baseline: 2.8269x; 1.7636x over previous
#include <cuda_runtime.h>
#include <cuda_bf16.h>
#include <cstdint>

#define B_   16
#define N_   1029
#define H_   16
#define HD_  64
#define D_   1024
#define M_TOT (B_ * N_)     // 16464
#define PREFIX_ 5           // N - 1024
#define SCALE_ 0.125f       // HD^-0.5
#define NPAD  1088          // 17 * 64

// ---------------- scratch (allocation-free: device globals) ----------------
__device__ float g_P[(size_t)M_TOT * D_];                   // projection temp [M, D]
__device__ __nv_bfloat16 g_Xhi[(size_t)M_TOT * D_];         // split GEMM input hi
__device__ __nv_bfloat16 g_Xlo[(size_t)M_TOT * D_];
__device__ __nv_bfloat16 g_Whi[(size_t)4 * D_ * D_];
__device__ __nv_bfloat16 g_Wlo[(size_t)4 * D_ * D_];
__device__ __nv_bfloat16 g_Qh[(size_t)B_ * H_ * NPAD * HD_];  // [bh, NPAD, 64]
__device__ __nv_bfloat16 g_Ql[(size_t)B_ * H_ * NPAD * HD_];
__device__ __nv_bfloat16 g_Kh[(size_t)B_ * H_ * NPAD * HD_];
__device__ __nv_bfloat16 g_Kl[(size_t)B_ * H_ * NPAD * HD_];
__device__ __nv_bfloat16 g_Vth[(size_t)B_ * H_ * HD_ * NPAD]; // [bh, 64, NPAD]
__device__ __nv_bfloat16 g_Vtl[(size_t)B_ * H_ * HD_ * NPAD];

// ======================= PTX helpers (arch-agnostic) =======================
__device__ __forceinline__ uint32_t smem_u32(const void* p) {
    uint32_t a;
    asm("{ .reg .u64 t; cvta.to.shared.u64 t, %1; cvt.u32.u64 %0, t; }"
        : "=r"(a) : "l"(p));
    return a;
}
__device__ __forceinline__ void cp16(uint32_t dst, const void* src, int src_bytes) {
    asm volatile("cp.async.cg.shared.global [%0], [%1], 16, %2;"
                 :: "r"(dst), "l"(src), "r"(src_bytes));
}
#define CP_COMMIT() asm volatile("cp.async.commit_group;")
#define CP_WAIT1()  asm volatile("cp.async.wait_group 1;")
#define CP_WAIT0()  asm volatile("cp.async.wait_group 0;")

__device__ __forceinline__ void ldm4(uint32_t& r0, uint32_t& r1, uint32_t& r2,
                                     uint32_t& r3, uint32_t addr) {
    asm volatile("ldmatrix.sync.aligned.m8n8.x4.shared.b16 {%0,%1,%2,%3}, [%4];"
                 : "=r"(r0), "=r"(r1), "=r"(r2), "=r"(r3) : "r"(addr));
}
__device__ __forceinline__ void mma16816(float* c, const uint32_t* a,
                                         uint32_t b0, uint32_t b1) {
    asm volatile(
        "mma.sync.aligned.m16n8k16.row.col.f32.bf16.bf16.f32 "
        "{%0,%1,%2,%3}, {%4,%5,%6,%7}, {%8,%9}, {%0,%1,%2,%3};"
        : "+f"(c[0]), "+f"(c[1]), "+f"(c[2]), "+f"(c[3])
        : "r"(a[0]), "r"(a[1]), "r"(a[2]), "r"(a[3]), "r"(b0), "r"(b1));
}
__device__ __forceinline__ uint32_t pack_bf16(float lo, float hi) {
    __nv_bfloat16 a = __float2bfloat16(lo), b = __float2bfloat16(hi);
    return (uint32_t)*(unsigned short*)&a | ((uint32_t)*(unsigned short*)&b << 16);
}

// =============== fp32 -> (hi, lo) bf16 split conversion ====================
__global__ void f32_split_kernel(const float* __restrict__ x,
                                 __nv_bfloat16* __restrict__ hi,
                                 __nv_bfloat16* __restrict__ lo, int n4) {
    int i = blockIdx.x * blockDim.x + threadIdx.x;
    if (i >= n4) return;
    float4 v = ((const float4*)x)[i];
    __nv_bfloat16 h0 = __float2bfloat16(v.x), h1 = __float2bfloat16(v.y);
    __nv_bfloat16 h2 = __float2bfloat16(v.z), h3 = __float2bfloat16(v.w);
    __nv_bfloat16 l0 = __float2bfloat16(v.x - __bfloat162float(h0));
    __nv_bfloat16 l1 = __float2bfloat16(v.y - __bfloat162float(h1));
    __nv_bfloat16 l2 = __float2bfloat16(v.z - __bfloat162float(h2));
    __nv_bfloat16 l3 = __float2bfloat16(v.w - __bfloat162float(h3));
    ushort4 hh, ll;
    hh.x = *(unsigned short*)&h0; hh.y = *(unsigned short*)&h1;
    hh.z = *(unsigned short*)&h2; hh.w = *(unsigned short*)&h3;
    ll.x = *(unsigned short*)&l0; ll.y = *(unsigned short*)&l1;
    ll.z = *(unsigned short*)&l2; ll.w = *(unsigned short*)&l3;
    ((ushort4*)hi)[i] = hh;
    ((ushort4*)lo)[i] = ll;
}

// ========== warp-MMA split-bf16 GEMM: Y[M,1024] = X @ W^T + b =============
#define KC        32
#define ASTRIDE   40
#define ARR_ELE   (128 * ASTRIDE)
#define ARR_B     (ARR_ELE * 2)             // 10240 bytes
#define STAGE_B   (4 * ARR_B)               // 40960 bytes
#define GSMEM     (2 * STAGE_B)             // 81920 bytes

__global__ __launch_bounds__(256, 1)
void gemm_mma_kernel(const __nv_bfloat16* __restrict__ Xhi,
                     const __nv_bfloat16* __restrict__ Xlo,
                     const __nv_bfloat16* __restrict__ Whi,
                     const __nv_bfloat16* __restrict__ Wlo,
                     const float* __restrict__ bias,
                     float* __restrict__ Y, int Mrows) {
    extern __shared__ __align__(16) char sm[];
    const uint32_t smb = smem_u32(sm);
    const int tid = threadIdx.x;
    const int wid = tid >> 5, lane = tid & 31;
    const int bm = blockIdx.y * 128;
    const int bn = blockIdx.x * 128;
    const int wm = (wid >> 1) * 32;
    const int wn = (wid & 1) * 64;

    const int r0i = tid >> 2, kg0 = tid & 3;
    const int r1i = (tid + 256) >> 2, kg1 = tid & 3;
    const int ar0 = bm + r0i, ar1 = bm + r1i;
    const int p0 = (ar0 < Mrows) ? 16 : 0;
    const int p1 = (ar1 < Mrows) ? 16 : 0;
    const size_t ga0 = (size_t)(p0 ? ar0 : 0) * D_;
    const size_t ga1 = (size_t)(p1 ? ar1 : 0) * D_;
    const size_t gb0 = (size_t)(bn + r0i) * D_;
    const size_t gb1 = (size_t)(bn + r1i) * D_;
    const uint32_t so0 = (uint32_t)(r0i * ASTRIDE + kg0 * 8) * 2;
    const uint32_t so1 = (uint32_t)(r1i * ASTRIDE + kg1 * 8) * 2;

    const int li = lane & 7, ti = lane >> 3;
    int rowA[2], rowB[4];
#pragma unroll
    for (int mt = 0; mt < 2; mt++)
        rowA[mt] = (wm + mt * 16 + li + (ti & 1) * 8) * ASTRIDE + (ti >> 1) * 8;
#pragma unroll
    for (int np = 0; np < 4; np++)
        rowB[np] = (wn + np * 16 + li + (ti >> 1) * 8) * ASTRIDE + (ti & 1) * 8;

    float acc[2][8][4];
#pragma unroll
    for (int mt = 0; mt < 2; mt++)
#pragma unroll
        for (int nt = 0; nt < 8; nt++)
#pragma unroll
            for (int e = 0; e < 4; e++) acc[mt][nt][e] = 0.f;

    auto load_chunk = [&](int c) {
        const int kof = c * KC;
        const uint32_t st = smb + (c & 1) * STAGE_B;
        cp16(st + 0 * ARR_B + so0, Xhi + ga0 + kof + kg0 * 8, p0);
        cp16(st + 0 * ARR_B + so1, Xhi + ga1 + kof + kg1 * 8, p1);
        cp16(st + 1 * ARR_B + so0, Xlo + ga0 + kof + kg0 * 8, p0);
        cp16(st + 1 * ARR_B + so1, Xlo + ga1 + kof + kg1 * 8, p1);
        cp16(st + 2 * ARR_B + so0, Whi + gb0 + kof + kg0 * 8, 16);
        cp16(st + 2 * ARR_B + so1, Whi + gb1 + kof + kg1 * 8, 16);
        cp16(st + 3 * ARR_B + so0, Wlo + gb0 + kof + kg0 * 8, 16);
        cp16(st + 3 * ARR_B + so1, Wlo + gb1 + kof + kg1 * 8, 16);
        CP_COMMIT();
    };

    load_chunk(0);

    const int NCH = D_ / KC;
    for (int c = 0; c < NCH; c++) {
        if (c + 1 < NCH) { load_chunk(c + 1); CP_WAIT1(); }
        else            { CP_WAIT0(); }
        __syncthreads();

        const uint32_t st = smb + (c & 1) * STAGE_B;
#pragma unroll
        for (int k16 = 0; k16 < KC; k16 += 16) {
            uint32_t ahi[2][4], alo[2][4];
#pragma unroll
            for (int mt = 0; mt < 2; mt++) {
                uint32_t aad = st + 0 * ARR_B + (uint32_t)(rowA[mt] + k16) * 2;
                ldm4(ahi[mt][0], ahi[mt][1], ahi[mt][2], ahi[mt][3], aad);
                uint32_t lad = st + 1 * ARR_B + (uint32_t)(rowA[mt] + k16) * 2;
                ldm4(alo[mt][0], alo[mt][1], alo[mt][2], alo[mt][3], lad);
            }
#pragma unroll
            for (int np = 0; np < 4; np++) {
                uint32_t bh0, bh1, bh2, bh3, bl0, bl1, bl2, bl3;
                uint32_t bad = st + 2 * ARR_B + (uint32_t)(rowB[np] + k16) * 2;
                ldm4(bh0, bh1, bh2, bh3, bad);
                uint32_t bld = st + 3 * ARR_B + (uint32_t)(rowB[np] + k16) * 2;
                ldm4(bl0, bl1, bl2, bl3, bld);
#pragma unroll
                for (int mt = 0; mt < 2; mt++) {
                    mma16816(acc[mt][2 * np + 0], ahi[mt], bh0, bh1);
                    mma16816(acc[mt][2 * np + 1], ahi[mt], bh2, bh3);
                    mma16816(acc[mt][2 * np + 0], ahi[mt], bl0, bl1);
                    mma16816(acc[mt][2 * np + 1], ahi[mt], bl2, bl3);
                    mma16816(acc[mt][2 * np + 0], alo[mt], bh0, bh1);
                    mma16816(acc[mt][2 * np + 1], alo[mt], bh2, bh3);
                }
            }
        }
        __syncthreads();
    }

    const int cg = lane >> 2, tg = lane & 3;
#pragma unroll
    for (int mt = 0; mt < 2; mt++) {
        const int r0 = bm + wm + mt * 16 + cg;
        const int r1 = r0 + 8;
#pragma unroll
        for (int nt = 0; nt < 8; nt++) {
            const int col = bn + wn + nt * 8 + tg * 2;
            const float b0v = bias[col], b1v = bias[col + 1];
            if (r0 < Mrows) {
                float2 o = make_float2(acc[mt][nt][0] + b0v, acc[mt][nt][1] + b1v);
                *(float2*)(Y + (size_t)r0 * D_ + col) = o;
            }
            if (r1 < Mrows) {
                float2 o = make_float2(acc[mt][nt][2] + b0v, acc[mt][nt][3] + b1v);
                *(float2*)(Y + (size_t)r1 * D_ + col) = o;
            }
        }
    }
}

// ------- RoPE + transpose + bf16 hi/lo split into padded [bh,NPAD,64] ------
__global__ void rope_split_kernel(const float* __restrict__ P,
                                  const float* __restrict__ sinp,
                                  const float* __restrict__ cosp,
                                  __nv_bfloat16* __restrict__ Oh,
                                  __nv_bfloat16* __restrict__ Ol,
                                  int apply_rope) {
    size_t i = (size_t)blockIdx.x * blockDim.x + threadIdx.x;
    const size_t total = (size_t)B_ * NPAD * H_ * 32;
    if (i >= total) return;
    int d2 = (int)(i & 31);
    size_t r = i >> 5;
    int h = (int)(r % H_); r /= H_;
    int n = (int)(r % NPAD);
    int b = (int)(r / NPAD);

    float y1 = 0.f, y2 = 0.f;
    if (n < N_) {
        const float* src = P + ((size_t)b * N_ + n) * D_ + h * HD_;
        float x1 = src[d2], x2 = src[d2 + 32];
        y1 = x1; y2 = x2;
        if (apply_rope && n >= PREFIX_) {
            int p = n - PREFIX_;
            float c1 = cosp[p * HD_ + d2], c2 = cosp[p * HD_ + d2 + 32];
            float s1 = sinp[p * HD_ + d2], s2 = sinp[p * HD_ + d2 + 32];
            y1 = fmaf(x1, c1, -x2 * s1);
            y2 = fmaf(x2, c2,  x1 * s2);
        }
    }
    size_t dst = ((size_t)(b * H_ + h) * NPAD + n) * HD_;
    __nv_bfloat16 h1 = __float2bfloat16(y1);
    __nv_bfloat16 h2 = __float2bfloat16(y2);
    Oh[dst + d2]      = h1;
    Oh[dst + d2 + 32] = h2;
    Ol[dst + d2]      = __float2bfloat16(y1 - __bfloat162float(h1));
    Ol[dst + d2 + 32] = __float2bfloat16(y2 - __bfloat162float(h2));
}

// ------- V: transpose + split into [bh, 64, NPAD] (SMEM-tiled) -------------
__global__ void vsplit_t_kernel(const float* __restrict__ P,
                                __nv_bfloat16* __restrict__ Vh,
                                __nv_bfloat16* __restrict__ Vl) {
    __shared__ float tile[32][33];
    const int bh = blockIdx.z, dt = blockIdx.y, nt = blockIdx.x;
    const int tx = threadIdx.x, ty = threadIdx.y;
    const int b = bh >> 4, h = bh & 15;

    int n = nt * 32 + ty, d = dt * 32 + tx;
    float v = 0.f;
    if (n < N_) v = P[((size_t)b * N_ + n) * D_ + h * HD_ + d];
    tile[ty][tx] = v;
    __syncthreads();

    int d2 = dt * 32 + ty, n2 = nt * 32 + tx;
    float x = tile[tx][ty];
    __nv_bfloat16 hi = __float2bfloat16(x);
    size_t dst = ((size_t)bh * HD_ + d2) * NPAD + n2;
    Vh[dst] = hi;
    Vl[dst] = __float2bfloat16(x - __bfloat162float(hi));
}

// ---------------- MMA flash attention: 64 q-rows per CTA, 4 warps ----------
// SMEM rows hold full HD=64 bf16 -> stride 72 (64 data + 8 skew), conflict-free
#define ASTA  72
#define AARR  (64 * ASTA * 2)   // 9216 bytes per array
#define ASMEM (10 * AARR)       // 92160 bytes total (dynamic)

__global__ __launch_bounds__(128)
void attn_mma_kernel(const __nv_bfloat16* __restrict__ Qh,
                     const __nv_bfloat16* __restrict__ Ql,
                     const __nv_bfloat16* __restrict__ Kh,
                     const __nv_bfloat16* __restrict__ Kl,
                     const __nv_bfloat16* __restrict__ Vh,
                     const __nv_bfloat16* __restrict__ Vl,
                     __nv_bfloat16* __restrict__ Ohi,
                     __nv_bfloat16* __restrict__ Olo) {
    extern __shared__ __align__(16) char asm_[];
    const uint32_t smb = smem_u32(asm_);
    const int tid = threadIdx.x, w = tid >> 5, lane = tid & 31;
    const int li = lane & 7, ti = lane >> 3;
    const int cg = lane >> 2, tg = lane & 3;
    const int bh = blockIdx.y;
    const int qt = blockIdx.x * 64;
    const int b = bh >> 4, h = bh & 15;

    const uint32_t QHS = smb, QLS = smb + AARR;

    // ---- load Q tile (rows qt..qt+63) ----
    {
        const size_t gq = ((size_t)bh * NPAD + qt) * HD_;
        for (int c = tid; c < 512; c += 128) {
            int r = c >> 3, k8 = c & 7;
            uint32_t off = (uint32_t)(r * ASTA + k8 * 8) * 2;
            cp16(QHS + off, Qh + gq + r * HD_ + k8 * 8, 16);
            cp16(QLS + off, Ql + gq + r * HD_ + k8 * 8, 16);
        }
        CP_COMMIT();
    }

    auto load_kv = [&](int t) {
        const uint32_t st = smb + 2 * AARR + (t & 1) * 4 * AARR;
        const int kt = t * 64;
        const size_t gk = ((size_t)bh * NPAD + kt) * HD_;
        const size_t gv = (size_t)bh * HD_ * NPAD + kt;
        for (int c = tid; c < 512; c += 128) {
            int r = c >> 3, k8 = c & 7;
            uint32_t off = (uint32_t)(r * ASTA + k8 * 8) * 2;
            cp16(st + 0 * AARR + off, Kh + gk + r * HD_ + k8 * 8, 16);
            cp16(st + 1 * AARR + off, Kl + gk + r * HD_ + k8 * 8, 16);
            cp16(st + 2 * AARR + off, Vh + gv + (size_t)r * NPAD + k8 * 8, 16);
            cp16(st + 3 * AARR + off, Vl + gv + (size_t)r * NPAD + k8 * 8, 16);
        }
        CP_COMMIT();
    };

    load_kv(0);

    float o[8][4];
#pragma unroll
    for (int nt = 0; nt < 8; nt++)
#pragma unroll
        for (int e = 0; e < 4; e++) o[nt][e] = 0.f;
    float m0 = -1e30f, m1 = -1e30f, l0 = 0.f, l1 = 0.f;

    const uint32_t aoff_base = (uint32_t)((16 * w + li + (ti & 1) * 8) * ASTA + (ti >> 1) * 8) * 2;
    uint32_t boff[4];
#pragma unroll
    for (int np = 0; np < 4; np++)
        boff[np] = (uint32_t)((np * 16 + li + (ti >> 1) * 8) * ASTA + (ti & 1) * 8) * 2;

    const int NT = NPAD / 64;  // 17
    for (int t = 0; t < NT; t++) {
        if (t + 1 < NT) { load_kv(t + 1); CP_WAIT1(); }
        else            { CP_WAIT0(); }
        __syncthreads();
        const uint32_t st = smb + 2 * AARR + (t & 1) * 4 * AARR;

        // ---- S = Q K^T (split 3x) ----
        float sacc[8][4];
#pragma unroll
        for (int nt = 0; nt < 8; nt++)
#pragma unroll
            for (int e = 0; e < 4; e++) sacc[nt][e] = 0.f;

#pragma unroll
        for (int kk = 0; kk < 4; kk++) {
            uint32_t qh[4], ql[4];
            ldm4(qh[0], qh[1], qh[2], qh[3], QHS + aoff_base + kk * 32);
            ldm4(ql[0], ql[1], ql[2], ql[3], QLS + aoff_base + kk * 32);
#pragma unroll
            for (int np = 0; np < 4; np++) {
                uint32_t kh0, kh1, kh2, kh3, kl0, kl1, kl2, kl3;
                ldm4(kh0, kh1, kh2, kh3, st + 0 * AARR + boff[np] + kk * 32);
                ldm4(kl0, kl1, kl2, kl3, st + 1 * AARR + boff[np] + kk * 32);
                mma16816(sacc[2 * np + 0], qh, kh0, kh1);
                mma16816(sacc[2 * np + 1], qh, kh2, kh3);
                mma16816(sacc[2 * np + 0], qh, kl0, kl1);
                mma16816(sacc[2 * np + 1], qh, kl2, kl3);
                mma16816(sacc[2 * np + 0], ql, kh0, kh1);
                mma16816(sacc[2 * np + 1], ql, kh2, kh3);
            }
        }

        // ---- online softmax ----
        const int colbase = t * 64 + 2 * tg;
        float tm0 = -1e30f, tm1 = -1e30f;
#pragma unroll
        for (int nt = 0; nt < 8; nt++) {
            int c0 = colbase + nt * 8;
            float s0 = (c0     < N_) ? sacc[nt][0] * SCALE_ : -1e30f;
            float s1 = (c0 + 1 < N_) ? sacc[nt][1] * SCALE_ : -1e30f;
            float s2 = (c0     < N_) ? sacc[nt][2] * SCALE_ : -1e30f;
            float s3 = (c0 + 1 < N_) ? sacc[nt][3] * SCALE_ : -1e30f;
            sacc[nt][0] = s0; sacc[nt][1] = s1; sacc[nt][2] = s2; sacc[nt][3] = s3;
            tm0 = fmaxf(tm0, fmaxf(s0, s1));
            tm1 = fmaxf(tm1, fmaxf(s2, s3));
        }
        tm0 = fmaxf(tm0, __shfl_xor_sync(0xffffffffu, tm0, 1));
        tm0 = fmaxf(tm0, __shfl_xor_sync(0xffffffffu, tm0, 2));
        tm1 = fmaxf(tm1, __shfl_xor_sync(0xffffffffu, tm1, 1));
        tm1 = fmaxf(tm1, __shfl_xor_sync(0xffffffffu, tm1, 2));
        float nm0 = fmaxf(m0, tm0), nm1 = fmaxf(m1, tm1);
        float cr0 = __expf(m0 - nm0), cr1 = __expf(m1 - nm1);
        m0 = nm0; m1 = nm1;

        uint32_t phf[4][4], plf[4][4];
        float rs0 = 0.f, rs1 = 0.f;
#pragma unroll
        for (int nt = 0; nt < 8; nt++) {
            float p0 = __expf(sacc[nt][0] - nm0);
            float p1 = __expf(sacc[nt][1] - nm0);
            float p2 = __expf(sacc[nt][2] - nm1);
            float p3 = __expf(sacc[nt][3] - nm1);
            rs0 += p0 + p1; rs1 += p2 + p3;
            float h0 = __bfloat162float(__float2bfloat16(p0));
            float h1 = __bfloat162float(__float2bfloat16(p1));
            float h2 = __bfloat162float(__float2bfloat16(p2));
            float h3 = __bfloat162float(__float2bfloat16(p3));
            uint32_t ph01 = pack_bf16(h0, h1);
            uint32_t ph23 = pack_bf16(h2, h3);
            uint32_t pl01 = pack_bf16(p0 - h0, p1 - h1);
            uint32_t pl23 = pack_bf16(p2 - h2, p3 - h3);
            int kk = nt >> 1;
            if ((nt & 1) == 0) {
                phf[kk][0] = ph01; phf[kk][1] = ph23;
                plf[kk][0] = pl01; plf[kk][1] = pl23;
            } else {
                phf[kk][2] = ph01; phf[kk][3] = ph23;
                plf[kk][2] = pl01; plf[kk][3] = pl23;
            }
        }
        rs0 += __shfl_xor_sync(0xffffffffu, rs0, 1);
        rs0 += __shfl_xor_sync(0xffffffffu, rs0, 2);
        rs1 += __shfl_xor_sync(0xffffffffu, rs1, 1);
        rs1 += __shfl_xor_sync(0xffffffffu, rs1, 2);
        l0 = l0 * cr0 + rs0;
        l1 = l1 * cr1 + rs1;
#pragma unroll
        for (int nt = 0; nt < 8; nt++) {
            o[nt][0] *= cr0; o[nt][1] *= cr0;
            o[nt][2] *= cr1; o[nt][3] *= cr1;
        }

        // ---- O += P V (split 3x) ----
#pragma unroll
        for (int kk = 0; kk < 4; kk++) {
#pragma unroll
            for (int np = 0; np < 4; np++) {
                uint32_t vh0, vh1, vh2, vh3, vl0, vl1, vl2, vl3;
                ldm4(vh0, vh1, vh2, vh3, st + 2 * AARR + boff[np] + kk * 32);
                ldm4(vl0, vl1, vl2, vl3, st + 3 * AARR + boff[np] + kk * 32);
                mma16816(o[2 * np + 0], phf[kk], vh0, vh1);
                mma16816(o[2 * np + 1], phf[kk], vh2, vh3);
                mma16816(o[2 * np + 0], phf[kk], vl0, vl1);
                mma16816(o[2 * np + 1], phf[kk], vl2, vl3);
                mma16816(o[2 * np + 0], plf[kk], vh0, vh1);
                mma16816(o[2 * np + 1], plf[kk], vh2, vh3);
            }
        }
        __syncthreads();
    }

    // ---- epilogue: normalize, split to bf16 hi/lo GEMM input ----
    const float inv0 = 1.f / l0, inv1 = 1.f / l1;
    const int r0 = qt + 16 * w + cg, r1 = r0 + 8;
#pragma unroll
    for (int nt = 0; nt < 8; nt++) {
        const int col = h * HD_ + nt * 8 + 2 * tg;
        if (r0 < N_) {
            float x0 = o[nt][0] * inv0, x1 = o[nt][1] * inv0;
            float h0 = __bfloat162float(__float2bfloat16(x0));
            float h1 = __bfloat162float(__float2bfloat16(x1));
            size_t dst = (size_t)(b * N_ + r0) * D_ + col;
            *(uint32_t*)(Ohi + dst) = pack_bf16(h0, h1);
            *(uint32_t*)(Olo + dst) = pack_bf16(x0 - h0, x1 - h1);
        }
        if (r1 < N_) {
            float x2 = o[nt][2] * inv1, x3 = o[nt][3] * inv1;
            float h2 = __bfloat162float(__float2bfloat16(x2));
            float h3 = __bfloat162float(__float2bfloat16(x3));
            size_t dst = (size_t)(b * N_ + r1) * D_ + col;
            *(uint32_t*)(Ohi + dst) = pack_bf16(h2, h3);
            *(uint32_t*)(Olo + dst) = pack_bf16(x2 - h2, x3 - h3);
        }
    }
}

// --------------------------------- launcher --------------------------------
extern "C" void kernel_launch(void* const* d_in, const int* in_sizes, int n_in,
                              void* d_out, int out_size) {
    const float* hs = (const float*)d_in[0];
    const float* sn = (const float*)d_in[1];
    const float* cs = (const float*)d_in[2];
    const float* Wq = (const float*)d_in[3];
    const float* bq = (const float*)d_in[4];
    const float* Wk = (const float*)d_in[5];
    const float* bk = (const float*)d_in[6];
    const float* Wv = (const float*)d_in[7];
    const float* bv = (const float*)d_in[8];
    const float* Wo = (const float*)d_in[9];
    const float* bo = (const float*)d_in[10];
    float* out = (float*)d_out;

    float* P;
    __nv_bfloat16 *Xhi, *Xlo, *Whi, *Wlo, *Qh, *Ql, *Kh, *Kl, *Vth, *Vtl;
    cudaGetSymbolAddress((void**)&P,   g_P);
    cudaGetSymbolAddress((void**)&Xhi, g_Xhi);
    cudaGetSymbolAddress((void**)&Xlo, g_Xlo);
    cudaGetSymbolAddress((void**)&Whi, g_Whi);
    cudaGetSymbolAddress((void**)&Wlo, g_Wlo);
    cudaGetSymbolAddress((void**)&Qh,  g_Qh);
    cudaGetSymbolAddress((void**)&Ql,  g_Ql);
    cudaGetSymbolAddress((void**)&Kh,  g_Kh);
    cudaGetSymbolAddress((void**)&Kl,  g_Kl);
    cudaGetSymbolAddress((void**)&Vth, g_Vth);
    cudaGetSymbolAddress((void**)&Vtl, g_Vtl);

    cudaFuncSetAttribute(gemm_mma_kernel,
                         cudaFuncAttributeMaxDynamicSharedMemorySize, GSMEM);
    cudaFuncSetAttribute(attn_mma_kernel,
                         cudaFuncAttributeMaxDynamicSharedMemorySize, ASMEM);

    const int n4_hs = (M_TOT * D_) / 4;
    const int n4_w  = (D_ * D_) / 4;
    const size_t WN = (size_t)D_ * D_;

    dim3 cblk(256);
    dim3 cgrid_hs((n4_hs + 255) / 256), cgrid_w((n4_w + 255) / 256);
    dim3 ggrid(D_ / 128, (M_TOT + 127) / 128), gblk(256);
    const size_t rope_total = (size_t)B_ * NPAD * H_ * 32;
    dim3 rgrid((unsigned)((rope_total + 255) / 256)), rblk(256);
    dim3 vgrid(NPAD / 32, HD_ / 32, B_ * H_), vblk(32, 32);
    dim3 agrid(NPAD / 64, B_ * H_), ablk(128);

    f32_split_kernel<<<cgrid_hs, cblk>>>(hs, Xhi, Xlo, n4_hs);
    f32_split_kernel<<<cgrid_w, cblk>>>(Wq, Whi + 0 * WN, Wlo + 0 * WN, n4_w);
    f32_split_kernel<<<cgrid_w, cblk>>>(Wk, Whi + 1 * WN, Wlo + 1 * WN, n4_w);
    f32_split_kernel<<<cgrid_w, cblk>>>(Wv, Whi + 2 * WN, Wlo + 2 * WN, n4_w);
    f32_split_kernel<<<cgrid_w, cblk>>>(Wo, Whi + 3 * WN, Wlo + 3 * WN, n4_w);

    gemm_mma_kernel<<<ggrid, gblk, GSMEM>>>(Xhi, Xlo, Whi + 0 * WN, Wlo + 0 * WN, bq, P, M_TOT);
    rope_split_kernel<<<rgrid, rblk>>>(P, sn, cs, Qh, Ql, 1);
    gemm_mma_kernel<<<ggrid, gblk, GSMEM>>>(Xhi, Xlo, Whi + 1 * WN, Wlo + 1 * WN, bk, P, M_TOT);
    rope_split_kernel<<<rgrid, rblk>>>(P, sn, cs, Kh, Kl, 1);
    gemm_mma_kernel<<<ggrid, gblk, GSMEM>>>(Xhi, Xlo, Whi + 2 * WN, Wlo + 2 * WN, bv, P, M_TOT);
    vsplit_t_kernel<<<vgrid, vblk>>>(P, Vth, Vtl);

    attn_mma_kernel<<<agrid, ablk, ASMEM>>>(Qh, Ql, Kh, Kl, Vth, Vtl, Xhi, Xlo);

    gemm_mma_kernel<<<ggrid, gblk, GSMEM>>>(Xhi, Xlo, Whi + 3 * WN, Wlo + 3 * WN, bo, out, M_TOT);
}

// round 13
// speedup vs baseline: 3.3088x; 1.1705x over previous
#include <cuda_runtime.h>
#include <cuda_bf16.h>
#include <cstdint>

#define B_   16
#define N_   1029
#define H_   16
#define HD_  64
#define D_   1024
#define M_TOT (B_ * N_)     // 16464
#define PREFIX_ 5           // N - 1024
#define SCALE_ 0.125f       // HD^-0.5
#define NPAD  1088          // 17 * 64

// ---------------- scratch (allocation-free: device globals) ----------------
__device__ __nv_bfloat16 g_Xhi[(size_t)M_TOT * D_];         // split GEMM input hi
__device__ __nv_bfloat16 g_Xlo[(size_t)M_TOT * D_];
__device__ __nv_bfloat16 g_Whi[(size_t)4 * D_ * D_];
__device__ __nv_bfloat16 g_Wlo[(size_t)4 * D_ * D_];
__device__ __nv_bfloat16 g_Qh[(size_t)B_ * H_ * NPAD * HD_];  // [bh, NPAD, 64]
__device__ __nv_bfloat16 g_Ql[(size_t)B_ * H_ * NPAD * HD_];
__device__ __nv_bfloat16 g_Kh[(size_t)B_ * H_ * NPAD * HD_];
__device__ __nv_bfloat16 g_Kl[(size_t)B_ * H_ * NPAD * HD_];
__device__ __nv_bfloat16 g_Vh[(size_t)B_ * H_ * NPAD * HD_];  // [bh, NPAD, 64]
__device__ __nv_bfloat16 g_Vl[(size_t)B_ * H_ * NPAD * HD_];

// ======================= PTX helpers (arch-agnostic) =======================
__device__ __forceinline__ uint32_t smem_u32(const void* p) {
    uint32_t a;
    asm("{ .reg .u64 t; cvta.to.shared.u64 t, %1; cvt.u32.u64 %0, t; }"
        : "=r"(a) : "l"(p));
    return a;
}
__device__ __forceinline__ void cp16(uint32_t dst, const void* src, int src_bytes) {
    asm volatile("cp.async.cg.shared.global [%0], [%1], 16, %2;"
                 :: "r"(dst), "l"(src), "r"(src_bytes));
}
#define CP_COMMIT() asm volatile("cp.async.commit_group;")
#define CP_WAIT1()  asm volatile("cp.async.wait_group 1;")
#define CP_WAIT0()  asm volatile("cp.async.wait_group 0;")

__device__ __forceinline__ void ldm4(uint32_t& r0, uint32_t& r1, uint32_t& r2,
                                     uint32_t& r3, uint32_t addr) {
    asm volatile("ldmatrix.sync.aligned.m8n8.x4.shared.b16 {%0,%1,%2,%3}, [%4];"
                 : "=r"(r0), "=r"(r1), "=r"(r2), "=r"(r3) : "r"(addr));
}
__device__ __forceinline__ void ldm4t(uint32_t& r0, uint32_t& r1, uint32_t& r2,
                                      uint32_t& r3, uint32_t addr) {
    asm volatile("ldmatrix.sync.aligned.m8n8.x4.trans.shared.b16 {%0,%1,%2,%3}, [%4];"
                 : "=r"(r0), "=r"(r1), "=r"(r2), "=r"(r3) : "r"(addr));
}
__device__ __forceinline__ void mma16816(float* c, const uint32_t* a,
                                         uint32_t b0, uint32_t b1) {
    asm volatile(
        "mma.sync.aligned.m16n8k16.row.col.f32.bf16.bf16.f32 "
        "{%0,%1,%2,%3}, {%4,%5,%6,%7}, {%8,%9}, {%0,%1,%2,%3};"
        : "+f"(c[0]), "+f"(c[1]), "+f"(c[2]), "+f"(c[3])
        : "r"(a[0]), "r"(a[1]), "r"(a[2]), "r"(a[3]), "r"(b0), "r"(b1));
}
__device__ __forceinline__ uint32_t pack_bf16(float lo, float hi) {
    __nv_bfloat16 a = __float2bfloat16(lo), b = __float2bfloat16(hi);
    return (uint32_t)*(unsigned short*)&a | ((uint32_t)*(unsigned short*)&b << 16);
}

// =============== fp32 -> (hi, lo) bf16 split conversion ====================
__global__ void f32_split_kernel(const float* __restrict__ x,
                                 __nv_bfloat16* __restrict__ hi,
                                 __nv_bfloat16* __restrict__ lo, int n4) {
    int i = blockIdx.x * blockDim.x + threadIdx.x;
    if (i >= n4) return;
    float4 v = ((const float4*)x)[i];
    __nv_bfloat16 h0 = __float2bfloat16(v.x), h1 = __float2bfloat16(v.y);
    __nv_bfloat16 h2 = __float2bfloat16(v.z), h3 = __float2bfloat16(v.w);
    __nv_bfloat16 l0 = __float2bfloat16(v.x - __bfloat162float(h0));
    __nv_bfloat16 l1 = __float2bfloat16(v.y - __bfloat162float(h1));
    __nv_bfloat16 l2 = __float2bfloat16(v.z - __bfloat162float(h2));
    __nv_bfloat16 l3 = __float2bfloat16(v.w - __bfloat162float(h3));
    ushort4 hh, ll;
    hh.x = *(unsigned short*)&h0; hh.y = *(unsigned short*)&h1;
    hh.z = *(unsigned short*)&h2; hh.w = *(unsigned short*)&h3;
    ll.x = *(unsigned short*)&l0; ll.y = *(unsigned short*)&l1;
    ll.z = *(unsigned short*)&l2; ll.w = *(unsigned short*)&l3;
    ((ushort4*)hi)[i] = hh;
    ((ushort4*)lo)[i] = ll;
}

// ========== warp-MMA split-bf16 GEMM, 64x64 warp tiles =====================
// CTA 128x128, 4 warps, 128 threads, 2 CTAs/SM. K chunks of 32, dbl-buffered.
// mode 1: fused QKV epilogue (rope + bf16 split). mode 0: fp32 Y = X W^T + b.
#define KC        32
#define ASTRIDE   40
#define ARR_ELE   (128 * ASTRIDE)
#define ARR_B     (ARR_ELE * 2)             // 10240 bytes
#define STAGE_B   (4 * ARR_B)               // 40960 bytes
#define GSMEM     (2 * STAGE_B)             // 81920 bytes

__global__ __launch_bounds__(128, 2)
void gemm_mma_kernel(const __nv_bfloat16* __restrict__ Xhi,
                     const __nv_bfloat16* __restrict__ Xlo,
                     const __nv_bfloat16* __restrict__ Whi,
                     const __nv_bfloat16* __restrict__ Wlo,
                     const float* __restrict__ bq,
                     const float* __restrict__ bk,
                     const float* __restrict__ bv,
                     const float* __restrict__ sinp,
                     const float* __restrict__ cosp,
                     float* __restrict__ Y,
                     __nv_bfloat16* __restrict__ Qh, __nv_bfloat16* __restrict__ Ql,
                     __nv_bfloat16* __restrict__ Kh, __nv_bfloat16* __restrict__ Kl,
                     __nv_bfloat16* __restrict__ Vh, __nv_bfloat16* __restrict__ Vl,
                     int Mrows, int mode) {
    extern __shared__ __align__(16) char sm[];
    const uint32_t smb = smem_u32(sm);
    const int tid = threadIdx.x;
    const int wid = tid >> 5, lane = tid & 31;
    const int bm = blockIdx.y * 128;
    const int bn = blockIdx.x * 128;
    const int wm = (wid >> 1) * 64;
    const int wn = (wid & 1) * 64;

    // ---- loader indexing: 4 uint4 per array per stage per thread ----
    int pA[4]; size_t gA[4], gW[4]; uint32_t sO[4];
#pragma unroll
    for (int t = 0; t < 4; t++) {
        int i = tid + t * 128;
        int r = i >> 2, kg = i & 3;
        int arow = bm + r;
        pA[t] = (arow < Mrows) ? 16 : 0;
        gA[t] = (size_t)(pA[t] ? arow : 0) * D_ + kg * 8;
        gW[t] = (size_t)(bn + r) * D_ + kg * 8;
        sO[t] = (uint32_t)(r * ASTRIDE + kg * 8) * 2;
    }

    const int li = lane & 7, ti = lane >> 3;
    int rowA[4], rowB[4];
#pragma unroll
    for (int mt = 0; mt < 4; mt++)
        rowA[mt] = (wm + mt * 16 + li + (ti & 1) * 8) * ASTRIDE + (ti >> 1) * 8;
#pragma unroll
    for (int np = 0; np < 4; np++)
        rowB[np] = (wn + np * 16 + li + (ti >> 1) * 8) * ASTRIDE + (ti & 1) * 8;

    float acc[4][8][4];
#pragma unroll
    for (int mt = 0; mt < 4; mt++)
#pragma unroll
        for (int nt = 0; nt < 8; nt++)
#pragma unroll
            for (int e = 0; e < 4; e++) acc[mt][nt][e] = 0.f;

    auto load_chunk = [&](int c) {
        const int kof = c * KC;
        const uint32_t st = smb + (c & 1) * STAGE_B;
#pragma unroll
        for (int t = 0; t < 4; t++) {
            cp16(st + 0 * ARR_B + sO[t], Xhi + gA[t] + kof, pA[t]);
            cp16(st + 1 * ARR_B + sO[t], Xlo + gA[t] + kof, pA[t]);
            cp16(st + 2 * ARR_B + sO[t], Whi + gW[t] + kof, 16);
            cp16(st + 3 * ARR_B + sO[t], Wlo + gW[t] + kof, 16);
        }
        CP_COMMIT();
    };

    load_chunk(0);

    const int NCH = D_ / KC;
    for (int c = 0; c < NCH; c++) {
        if (c + 1 < NCH) { load_chunk(c + 1); CP_WAIT1(); }
        else            { CP_WAIT0(); }
        __syncthreads();

        const uint32_t st = smb + (c & 1) * STAGE_B;
#pragma unroll
        for (int k16 = 0; k16 < KC; k16 += 16) {
            uint32_t ahi[4][4], alo[4][4];
#pragma unroll
            for (int mt = 0; mt < 4; mt++) {
                ldm4(ahi[mt][0], ahi[mt][1], ahi[mt][2], ahi[mt][3],
                     st + 0 * ARR_B + (uint32_t)(rowA[mt] + k16) * 2);
                ldm4(alo[mt][0], alo[mt][1], alo[mt][2], alo[mt][3],
                     st + 1 * ARR_B + (uint32_t)(rowA[mt] + k16) * 2);
            }
#pragma unroll
            for (int np = 0; np < 4; np++) {
                uint32_t bh0, bh1, bh2, bh3, bl0, bl1, bl2, bl3;
                ldm4(bh0, bh1, bh2, bh3, st + 2 * ARR_B + (uint32_t)(rowB[np] + k16) * 2);
                ldm4(bl0, bl1, bl2, bl3, st + 3 * ARR_B + (uint32_t)(rowB[np] + k16) * 2);
#pragma unroll
                for (int mt = 0; mt < 4; mt++) {
                    mma16816(acc[mt][2 * np + 0], ahi[mt], bh0, bh1);
                    mma16816(acc[mt][2 * np + 1], ahi[mt], bh2, bh3);
                    mma16816(acc[mt][2 * np + 0], ahi[mt], bl0, bl1);
                    mma16816(acc[mt][2 * np + 1], ahi[mt], bl2, bl3);
                    mma16816(acc[mt][2 * np + 0], alo[mt], bh0, bh1);
                    mma16816(acc[mt][2 * np + 1], alo[mt], bh2, bh3);
                }
            }
        }
        __syncthreads();
    }

    const int cg = lane >> 2, tg = lane & 3;

    if (mode == 0) {
        // ---- plain epilogue: Y = acc + bias (bias in bq) ----
#pragma unroll
        for (int mt = 0; mt < 4; mt++) {
            const int r0 = bm + wm + mt * 16 + cg;
            const int r1 = r0 + 8;
#pragma unroll
            for (int nt = 0; nt < 8; nt++) {
                const int col = bn + wn + nt * 8 + tg * 2;
                const float b0v = bq[col], b1v = bq[col + 1];
                if (r0 < Mrows) {
                    float2 o = make_float2(acc[mt][nt][0] + b0v, acc[mt][nt][1] + b1v);
                    *(float2*)(Y + (size_t)r0 * D_ + col) = o;
                }
                if (r1 < Mrows) {
                    float2 o = make_float2(acc[mt][nt][2] + b0v, acc[mt][nt][3] + b1v);
                    *(float2*)(Y + (size_t)r1 * D_ + col) = o;
                }
            }
        }
        return;
    }

    // ---- fused QKV epilogue: bias + (rope) + bf16 hi/lo split ----
    const int slab = bn >> 10;                       // 0=Q, 1=K, 2=V
    const int head = ((bn & 1023) + wn) >> 6;
    const float* bias = (slab == 0) ? bq : (slab == 1) ? bk : bv;
    __nv_bfloat16* Oh = (slab == 0) ? Qh : (slab == 1) ? Kh : Vh;
    __nv_bfloat16* Ol = (slab == 0) ? Ql : (slab == 1) ? Kl : Vl;
    const bool dorope = (slab < 2);

#pragma unroll
    for (int mt = 0; mt < 4; mt++) {
#pragma unroll
        for (int half = 0; half < 2; half++) {
            const int row = bm + wm + mt * 16 + cg + half * 8;
            if (row >= Mrows) continue;
            const int b = row / N_;
            const int n = row - b * N_;
            const size_t obase = ((size_t)(b * H_ + head) * NPAD + n) * HD_;
            const int p = n - PREFIX_;
            const bool rp = dorope && (p >= 0);
            const int eb = half * 2;
#pragma unroll
            for (int nt = 0; nt < 4; nt++) {
                const int d = nt * 8 + 2 * tg;
                float x1a = acc[mt][nt][eb]     + bias[head * 64 + d];
                float x1b = acc[mt][nt][eb + 1] + bias[head * 64 + d + 1];
                float x2a = acc[mt][nt + 4][eb]     + bias[head * 64 + d + 32];
                float x2b = acc[mt][nt + 4][eb + 1] + bias[head * 64 + d + 33];
                float y1a = x1a, y1b = x1b, y2a = x2a, y2b = x2b;
                if (rp) {
                    const float* cp_ = cosp + p * HD_;
                    const float* sp_ = sinp + p * HD_;
                    float c1a = cp_[d], c1b = cp_[d + 1];
                    float c2a = cp_[d + 32], c2b = cp_[d + 33];
                    float s1a = sp_[d], s1b = sp_[d + 1];
                    float s2a = sp_[d + 32], s2b = sp_[d + 33];
                    y1a = x1a * c1a - x2a * s1a;  y2a = x2a * c2a + x1a * s2a;
                    y1b = x1b * c1b - x2b * s1b;  y2b = x2b * c2b + x1b * s2b;
                }
                float h1a = __bfloat162float(__float2bfloat16(y1a));
                float h1b = __bfloat162float(__float2bfloat16(y1b));
                float h2a = __bfloat162float(__float2bfloat16(y2a));
                float h2b = __bfloat162float(__float2bfloat16(y2b));
                *(uint32_t*)(Oh + obase + d)      = pack_bf16(h1a, h1b);
                *(uint32_t*)(Ol + obase + d)      = pack_bf16(y1a - h1a, y1b - h1b);
                *(uint32_t*)(Oh + obase + d + 32) = pack_bf16(h2a, h2b);
                *(uint32_t*)(Ol + obase + d + 32) = pack_bf16(y2a - h2a, y2b - h2b);
            }
        }
    }
}

// ---------------- MMA flash attention: 64 q-rows per CTA, 4 warps ----------
#define ASTA  72
#define AARR  (64 * ASTA * 2)   // 9216 bytes per array
#define ASMEM (10 * AARR)       // 92160 bytes total (dynamic)

__global__ __launch_bounds__(128)
void attn_mma_kernel(const __nv_bfloat16* __restrict__ Qh,
                     const __nv_bfloat16* __restrict__ Ql,
                     const __nv_bfloat16* __restrict__ Kh,
                     const __nv_bfloat16* __restrict__ Kl,
                     const __nv_bfloat16* __restrict__ Vh,
                     const __nv_bfloat16* __restrict__ Vl,
                     __nv_bfloat16* __restrict__ Ohi,
                     __nv_bfloat16* __restrict__ Olo) {
    extern __shared__ __align__(16) char asm_[];
    const uint32_t smb = smem_u32(asm_);
    const int tid = threadIdx.x, w = tid >> 5, lane = tid & 31;
    const int li = lane & 7, ti = lane >> 3;
    const int cg = lane >> 2, tg = lane & 3;
    const int bh = blockIdx.y;
    const int qt = blockIdx.x * 64;
    const int b = bh >> 4, h = bh & 15;

    const uint32_t QHS = smb, QLS = smb + AARR;

    {
        const size_t gq = ((size_t)bh * NPAD + qt) * HD_;
        for (int c = tid; c < 512; c += 128) {
            int r = c >> 3, k8 = c & 7;
            uint32_t off = (uint32_t)(r * ASTA + k8 * 8) * 2;
            cp16(QHS + off, Qh + gq + r * HD_ + k8 * 8, 16);
            cp16(QLS + off, Ql + gq + r * HD_ + k8 * 8, 16);
        }
        CP_COMMIT();
    }

    auto load_kv = [&](int t) {
        const uint32_t st = smb + 2 * AARR + (t & 1) * 4 * AARR;
        const int kt = t * 64;
        const size_t gk = ((size_t)bh * NPAD + kt) * HD_;
        for (int c = tid; c < 512; c += 128) {
            int r = c >> 3, k8 = c & 7;
            uint32_t off = (uint32_t)(r * ASTA + k8 * 8) * 2;
            cp16(st + 0 * AARR + off, Kh + gk + r * HD_ + k8 * 8, 16);
            cp16(st + 1 * AARR + off, Kl + gk + r * HD_ + k8 * 8, 16);
            cp16(st + 2 * AARR + off, Vh + gk + r * HD_ + k8 * 8, 16);
            cp16(st + 3 * AARR + off, Vl + gk + r * HD_ + k8 * 8, 16);
        }
        CP_COMMIT();
    };

    load_kv(0);

    float o[8][4];
#pragma unroll
    for (int nt = 0; nt < 8; nt++)
#pragma unroll
        for (int e = 0; e < 4; e++) o[nt][e] = 0.f;
    float m0 = -1e30f, m1 = -1e30f, l0 = 0.f, l1 = 0.f;

    const uint32_t aoff_base = (uint32_t)((16 * w + li + (ti & 1) * 8) * ASTA + (ti >> 1) * 8) * 2;
    uint32_t boff[4], voff[4];
#pragma unroll
    for (int np = 0; np < 4; np++) {
        boff[np] = (uint32_t)((np * 16 + li + (ti >> 1) * 8) * ASTA + (ti & 1) * 8) * 2;
        voff[np] = (uint32_t)(((ti & 1) * 8 + li) * ASTA + np * 16 + (ti >> 1) * 8) * 2;
    }

    const int NT = NPAD / 64;  // 17
    for (int t = 0; t < NT; t++) {
        if (t + 1 < NT) { load_kv(t + 1); CP_WAIT1(); }
        else            { CP_WAIT0(); }
        __syncthreads();
        const uint32_t st = smb + 2 * AARR + (t & 1) * 4 * AARR;

        // ---- S = Q K^T (split 3x) ----
        float sacc[8][4];
#pragma unroll
        for (int nt = 0; nt < 8; nt++)
#pragma unroll
            for (int e = 0; e < 4; e++) sacc[nt][e] = 0.f;

#pragma unroll
        for (int kk = 0; kk < 4; kk++) {
            uint32_t qh[4], ql[4];
            ldm4(qh[0], qh[1], qh[2], qh[3], QHS + aoff_base + kk * 32);
            ldm4(ql[0], ql[1], ql[2], ql[3], QLS + aoff_base + kk * 32);
#pragma unroll
            for (int np = 0; np < 4; np++) {
                uint32_t kh0, kh1, kh2, kh3, kl0, kl1, kl2, kl3;
                ldm4(kh0, kh1, kh2, kh3, st + 0 * AARR + boff[np] + kk * 32);
                ldm4(kl0, kl1, kl2, kl3, st + 1 * AARR + boff[np] + kk * 32);
                mma16816(sacc[2 * np + 0], qh, kh0, kh1);
                mma16816(sacc[2 * np + 1], qh, kh2, kh3);
                mma16816(sacc[2 * np + 0], qh, kl0, kl1);
                mma16816(sacc[2 * np + 1], qh, kl2, kl3);
                mma16816(sacc[2 * np + 0], ql, kh0, kh1);
                mma16816(sacc[2 * np + 1], ql, kh2, kh3);
            }
        }

        // ---- online softmax ----
        const int colbase = t * 64 + 2 * tg;
        float tm0 = -1e30f, tm1 = -1e30f;
#pragma unroll
        for (int nt = 0; nt < 8; nt++) {
            int c0 = colbase + nt * 8;
            float s0 = (c0     < N_) ? sacc[nt][0] * SCALE_ : -1e30f;
            float s1 = (c0 + 1 < N_) ? sacc[nt][1] * SCALE_ : -1e30f;
            float s2 = (c0     < N_) ? sacc[nt][2] * SCALE_ : -1e30f;
            float s3 = (c0 + 1 < N_) ? sacc[nt][3] * SCALE_ : -1e30f;
            sacc[nt][0] = s0; sacc[nt][1] = s1; sacc[nt][2] = s2; sacc[nt][3] = s3;
            tm0 = fmaxf(tm0, fmaxf(s0, s1));
            tm1 = fmaxf(tm1, fmaxf(s2, s3));
        }
        tm0 = fmaxf(tm0, __shfl_xor_sync(0xffffffffu, tm0, 1));
        tm0 = fmaxf(tm0, __shfl_xor_sync(0xffffffffu, tm0, 2));
        tm1 = fmaxf(tm1, __shfl_xor_sync(0xffffffffu, tm1, 1));
        tm1 = fmaxf(tm1, __shfl_xor_sync(0xffffffffu, tm1, 2));
        float nm0 = fmaxf(m0, tm0), nm1 = fmaxf(m1, tm1);
        float cr0 = __expf(m0 - nm0), cr1 = __expf(m1 - nm1);
        m0 = nm0; m1 = nm1;

        uint32_t phf[4][4], plf[4][4];
        float rs0 = 0.f, rs1 = 0.f;
#pragma unroll
        for (int nt = 0; nt < 8; nt++) {
            float p0 = __expf(sacc[nt][0] - nm0);
            float p1 = __expf(sacc[nt][1] - nm0);
            float p2 = __expf(sacc[nt][2] - nm1);
            float p3 = __expf(sacc[nt][3] - nm1);
            rs0 += p0 + p1; rs1 += p2 + p3;
            float h0 = __bfloat162float(__float2bfloat16(p0));
            float h1 = __bfloat162float(__float2bfloat16(p1));
            float h2 = __bfloat162float(__float2bfloat16(p2));
            float h3 = __bfloat162float(__float2bfloat16(p3));
            uint32_t ph01 = pack_bf16(h0, h1);
            uint32_t ph23 = pack_bf16(h2, h3);
            uint32_t pl01 = pack_bf16(p0 - h0, p1 - h1);
            uint32_t pl23 = pack_bf16(p2 - h2, p3 - h3);
            int kk = nt >> 1;
            if ((nt & 1) == 0) {
                phf[kk][0] = ph01; phf[kk][1] = ph23;
                plf[kk][0] = pl01; plf[kk][1] = pl23;
            } else {
                phf[kk][2] = ph01; phf[kk][3] = ph23;
                plf[kk][2] = pl01; plf[kk][3] = pl23;
            }
        }
        rs0 += __shfl_xor_sync(0xffffffffu, rs0, 1);
        rs0 += __shfl_xor_sync(0xffffffffu, rs0, 2);
        rs1 += __shfl_xor_sync(0xffffffffu, rs1, 1);
        rs1 += __shfl_xor_sync(0xffffffffu, rs1, 2);
        l0 = l0 * cr0 + rs0;
        l1 = l1 * cr1 + rs1;
#pragma unroll
        for (int nt = 0; nt < 8; nt++) {
            o[nt][0] *= cr0; o[nt][1] *= cr0;
            o[nt][2] *= cr1; o[nt][3] *= cr1;
        }

        // ---- O += P V (split 3x, V via ldmatrix.trans) ----
#pragma unroll
        for (int kk = 0; kk < 4; kk++) {
            const uint32_t kadd = (uint32_t)(kk * 16 * ASTA) * 2;
#pragma unroll
            for (int np = 0; np < 4; np++) {
                uint32_t vh0, vh1, vh2, vh3, vl0, vl1, vl2, vl3;
                ldm4t(vh0, vh1, vh2, vh3, st + 2 * AARR + voff[np] + kadd);
                ldm4t(vl0, vl1, vl2, vl3, st + 3 * AARR + voff[np] + kadd);
                mma16816(o[2 * np + 0], phf[kk], vh0, vh1);
                mma16816(o[2 * np + 1], phf[kk], vh2, vh3);
                mma16816(o[2 * np + 0], phf[kk], vl0, vl1);
                mma16816(o[2 * np + 1], phf[kk], vl2, vl3);
                mma16816(o[2 * np + 0], plf[kk], vh0, vh1);
                mma16816(o[2 * np + 1], plf[kk], vh2, vh3);
            }
        }
        __syncthreads();
    }

    // ---- epilogue: normalize, split to bf16 hi/lo GEMM input ----
    const float inv0 = 1.f / l0, inv1 = 1.f / l1;
    const int r0 = qt + 16 * w + cg, r1 = r0 + 8;
#pragma unroll
    for (int nt = 0; nt < 8; nt++) {
        const int col = h * HD_ + nt * 8 + 2 * tg;
        if (r0 < N_) {
            float x0 = o[nt][0] * inv0, x1 = o[nt][1] * inv0;
            float h0 = __bfloat162float(__float2bfloat16(x0));
            float h1 = __bfloat162float(__float2bfloat16(x1));
            size_t dst = (size_t)(b * N_ + r0) * D_ + col;
            *(uint32_t*)(Ohi + dst) = pack_bf16(h0, h1);
            *(uint32_t*)(Olo + dst) = pack_bf16(x0 - h0, x1 - h1);
        }
        if (r1 < N_) {
            float x2 = o[nt][2] * inv1, x3 = o[nt][3] * inv1;
            float h2 = __bfloat162float(__float2bfloat16(x2));
            float h3 = __bfloat162float(__float2bfloat16(x3));
            size_t dst = (size_t)(b * N_ + r1) * D_ + col;
            *(uint32_t*)(Ohi + dst) = pack_bf16(h2, h3);
            *(uint32_t*)(Olo + dst) = pack_bf16(x2 - h2, x3 - h3);
        }
    }
}

// --------------------------------- launcher --------------------------------
extern "C" void kernel_launch(void* const* d_in, const int* in_sizes, int n_in,
                              void* d_out, int out_size) {
    const float* hs = (const float*)d_in[0];
    const float* sn = (const float*)d_in[1];
    const float* cs = (const float*)d_in[2];
    const float* Wq = (const float*)d_in[3];
    const float* bq = (const float*)d_in[4];
    const float* Wk = (const float*)d_in[5];
    const float* bk = (const float*)d_in[6];
    const float* Wv = (const float*)d_in[7];
    const float* bv = (const float*)d_in[8];
    const float* Wo = (const float*)d_in[9];
    const float* bo = (const float*)d_in[10];
    float* out = (float*)d_out;

    __nv_bfloat16 *Xhi, *Xlo, *Whi, *Wlo, *Qh, *Ql, *Kh, *Kl, *Vh, *Vl;
    cudaGetSymbolAddress((void**)&Xhi, g_Xhi);
    cudaGetSymbolAddress((void**)&Xlo, g_Xlo);
    cudaGetSymbolAddress((void**)&Whi, g_Whi);
    cudaGetSymbolAddress((void**)&Wlo, g_Wlo);
    cudaGetSymbolAddress((void**)&Qh,  g_Qh);
    cudaGetSymbolAddress((void**)&Ql,  g_Ql);
    cudaGetSymbolAddress((void**)&Kh,  g_Kh);
    cudaGetSymbolAddress((void**)&Kl,  g_Kl);
    cudaGetSymbolAddress((void**)&Vh,  g_Vh);
    cudaGetSymbolAddress((void**)&Vl,  g_Vl);

    cudaFuncSetAttribute(gemm_mma_kernel,
                         cudaFuncAttributeMaxDynamicSharedMemorySize, GSMEM);
    cudaFuncSetAttribute(attn_mma_kernel,
                         cudaFuncAttributeMaxDynamicSharedMemorySize, ASMEM);

    const int n4_hs = (M_TOT * D_) / 4;
    const int n4_w  = (D_ * D_) / 4;
    const size_t WN = (size_t)D_ * D_;

    dim3 cblk(256);
    dim3 cgrid_hs((n4_hs + 255) / 256), cgrid_w((n4_w + 255) / 256);
    dim3 qkvgrid(3 * D_ / 128, (M_TOT + 127) / 128), gblk(128);
    dim3 ogrid(D_ / 128, (M_TOT + 127) / 128);
    dim3 agrid(NPAD / 64, B_ * H_), ablk(128);

    f32_split_kernel<<<cgrid_hs, cblk>>>(hs, Xhi, Xlo, n4_hs);
    f32_split_kernel<<<cgrid_w, cblk>>>(Wq, Whi + 0 * WN, Wlo + 0 * WN, n4_w);
    f32_split_kernel<<<cgrid_w, cblk>>>(Wk, Whi + 1 * WN, Wlo + 1 * WN, n4_w);
    f32_split_kernel<<<cgrid_w, cblk>>>(Wv, Whi + 2 * WN, Wlo + 2 * WN, n4_w);
    f32_split_kernel<<<cgrid_w, cblk>>>(Wo, Whi + 3 * WN, Wlo + 3 * WN, n4_w);

    // fused QKV projection + bias + rope + split (one launch, N=3072)
    gemm_mma_kernel<<<qkvgrid, gblk, GSMEM>>>(
        Xhi, Xlo, Whi, Wlo, bq, bk, bv, sn, cs,
        nullptr, Qh, Ql, Kh, Kl, Vh, Vl, M_TOT, 1);

    attn_mma_kernel<<<agrid, ablk, ASMEM>>>(Qh, Ql, Kh, Kl, Vh, Vl, Xhi, Xlo);

    // O projection
    gemm_mma_kernel<<<ogrid, gblk, GSMEM>>>(
        Xhi, Xlo, Whi + 3 * WN, Wlo + 3 * WN, bo, nullptr, nullptr, nullptr, nullptr,
        out, nullptr, nullptr, nullptr, nullptr, nullptr, nullptr, M_TOT, 0);
}

// round 15
// speedup vs baseline: 3.4394x; 1.0395x over previous
#include <cuda_runtime.h>
#include <cuda_bf16.h>
#include <cstdint>

#define B_   16
#define N_   1029
#define H_   16
#define HD_  64
#define D_   1024
#define M_TOT (B_ * N_)     // 16464
#define PREFIX_ 5           // N - 1024
#define SCALE_ 0.125f       // HD^-0.5
#define NPAD  1088          // 17 * 64  (K/V padding)
#define NPADQ 1152          // 9 * 128  (Q padding)

// ---------------- scratch (allocation-free: device globals) ----------------
__device__ __nv_bfloat16 g_Xhi[(size_t)M_TOT * D_];         // split GEMM input hi
__device__ __nv_bfloat16 g_Xlo[(size_t)M_TOT * D_];
__device__ __nv_bfloat16 g_Whi[(size_t)4 * D_ * D_];
__device__ __nv_bfloat16 g_Wlo[(size_t)4 * D_ * D_];
__device__ __nv_bfloat16 g_Qh[(size_t)B_ * H_ * NPADQ * HD_]; // [bh, NPADQ, 64]
__device__ __nv_bfloat16 g_Ql[(size_t)B_ * H_ * NPADQ * HD_];
__device__ __nv_bfloat16 g_Kh[(size_t)B_ * H_ * NPAD * HD_];  // [bh, NPAD, 64]
__device__ __nv_bfloat16 g_Kl[(size_t)B_ * H_ * NPAD * HD_];
__device__ __nv_bfloat16 g_Vh[(size_t)B_ * H_ * NPAD * HD_];
__device__ __nv_bfloat16 g_Vl[(size_t)B_ * H_ * NPAD * HD_];

// ======================= PTX helpers (arch-agnostic) =======================
__device__ __forceinline__ uint32_t smem_u32(const void* p) {
    uint32_t a;
    asm("{ .reg .u64 t; cvta.to.shared.u64 t, %1; cvt.u32.u64 %0, t; }"
        : "=r"(a) : "l"(p));
    return a;
}
__device__ __forceinline__ void cp16(uint32_t dst, const void* src, int src_bytes) {
    asm volatile("cp.async.cg.shared.global [%0], [%1], 16, %2;"
                 :: "r"(dst), "l"(src), "r"(src_bytes));
}
#define CP_COMMIT() asm volatile("cp.async.commit_group;")
#define CP_WAIT1()  asm volatile("cp.async.wait_group 1;")
#define CP_WAIT0()  asm volatile("cp.async.wait_group 0;")

__device__ __forceinline__ void ldm4(uint32_t& r0, uint32_t& r1, uint32_t& r2,
                                     uint32_t& r3, uint32_t addr) {
    asm volatile("ldmatrix.sync.aligned.m8n8.x4.shared.b16 {%0,%1,%2,%3}, [%4];"
                 : "=r"(r0), "=r"(r1), "=r"(r2), "=r"(r3) : "r"(addr));
}
__device__ __forceinline__ void ldm4t(uint32_t& r0, uint32_t& r1, uint32_t& r2,
                                      uint32_t& r3, uint32_t addr) {
    asm volatile("ldmatrix.sync.aligned.m8n8.x4.trans.shared.b16 {%0,%1,%2,%3}, [%4];"
                 : "=r"(r0), "=r"(r1), "=r"(r2), "=r"(r3) : "r"(addr));
}
__device__ __forceinline__ void mma16816(float* c, const uint32_t* a,
                                         uint32_t b0, uint32_t b1) {
    asm volatile(
        "mma.sync.aligned.m16n8k16.row.col.f32.bf16.bf16.f32 "
        "{%0,%1,%2,%3}, {%4,%5,%6,%7}, {%8,%9}, {%0,%1,%2,%3};"
        : "+f"(c[0]), "+f"(c[1]), "+f"(c[2]), "+f"(c[3])
        : "r"(a[0]), "r"(a[1]), "r"(a[2]), "r"(a[3]), "r"(b0), "r"(b1));
}
__device__ __forceinline__ uint32_t pack_bf16(float lo, float hi) {
    __nv_bfloat16 a = __float2bfloat16(lo), b = __float2bfloat16(hi);
    return (uint32_t)*(unsigned short*)&a | ((uint32_t)*(unsigned short*)&b << 16);
}

// =============== fp32 -> (hi, lo) bf16 split conversion ====================
__device__ __forceinline__ void split4(const float4 v, ushort4& hh, ushort4& ll) {
    __nv_bfloat16 h0 = __float2bfloat16(v.x), h1 = __float2bfloat16(v.y);
    __nv_bfloat16 h2 = __float2bfloat16(v.z), h3 = __float2bfloat16(v.w);
    __nv_bfloat16 l0 = __float2bfloat16(v.x - __bfloat162float(h0));
    __nv_bfloat16 l1 = __float2bfloat16(v.y - __bfloat162float(h1));
    __nv_bfloat16 l2 = __float2bfloat16(v.z - __bfloat162float(h2));
    __nv_bfloat16 l3 = __float2bfloat16(v.w - __bfloat162float(h3));
    hh.x = *(unsigned short*)&h0; hh.y = *(unsigned short*)&h1;
    hh.z = *(unsigned short*)&h2; hh.w = *(unsigned short*)&h3;
    ll.x = *(unsigned short*)&l0; ll.y = *(unsigned short*)&l1;
    ll.z = *(unsigned short*)&l2; ll.w = *(unsigned short*)&l3;
}

__global__ void f32_split_kernel(const float* __restrict__ x,
                                 __nv_bfloat16* __restrict__ hi,
                                 __nv_bfloat16* __restrict__ lo, int n4) {
    int i = blockIdx.x * blockDim.x + threadIdx.x;
    if (i >= n4) return;
    ushort4 hh, ll;
    split4(((const float4*)x)[i], hh, ll);
    ((ushort4*)hi)[i] = hh;
    ((ushort4*)lo)[i] = ll;
}

// merged 4-weight split: Whi/Wlo are contiguous [4, D, D]
__global__ void w4_split_kernel(const float* __restrict__ w0,
                                const float* __restrict__ w1,
                                const float* __restrict__ w2,
                                const float* __restrict__ w3,
                                __nv_bfloat16* __restrict__ hi,
                                __nv_bfloat16* __restrict__ lo, int n4w) {
    int i = blockIdx.x * blockDim.x + threadIdx.x;
    if (i >= 4 * n4w) return;
    int seg = i / n4w, j = i - seg * n4w;
    const float* src = (seg == 0) ? w0 : (seg == 1) ? w1 : (seg == 2) ? w2 : w3;
    ushort4 hh, ll;
    split4(((const float4*)src)[j], hh, ll);
    ((ushort4*)hi)[i] = hh;
    ((ushort4*)lo)[i] = ll;
}

// ========== warp-MMA split-bf16 GEMM, 64x64 warp tiles =====================
#define KC        32
#define ASTRIDE   40
#define ARR_ELE   (128 * ASTRIDE)
#define ARR_B     (ARR_ELE * 2)             // 10240 bytes
#define STAGE_B   (4 * ARR_B)               // 40960 bytes
#define GSMEM     (2 * STAGE_B)             // 81920 bytes

__global__ __launch_bounds__(128, 2)
void gemm_mma_kernel(const __nv_bfloat16* __restrict__ Xhi,
                     const __nv_bfloat16* __restrict__ Xlo,
                     const __nv_bfloat16* __restrict__ Whi,
                     const __nv_bfloat16* __restrict__ Wlo,
                     const float* __restrict__ bq,
                     const float* __restrict__ bk,
                     const float* __restrict__ bv,
                     const float* __restrict__ sinp,
                     const float* __restrict__ cosp,
                     float* __restrict__ Y,
                     __nv_bfloat16* __restrict__ Qh, __nv_bfloat16* __restrict__ Ql,
                     __nv_bfloat16* __restrict__ Kh, __nv_bfloat16* __restrict__ Kl,
                     __nv_bfloat16* __restrict__ Vh, __nv_bfloat16* __restrict__ Vl,
                     int Mrows, int mode) {
    extern __shared__ __align__(16) char sm[];
    const uint32_t smb = smem_u32(sm);
    const int tid = threadIdx.x;
    const int wid = tid >> 5, lane = tid & 31;
    const int bm = blockIdx.y * 128;
    const int bn = blockIdx.x * 128;
    const int wm = (wid >> 1) * 64;
    const int wn = (wid & 1) * 64;

    int pA[4]; size_t gA[4], gW[4]; uint32_t sO[4];
#pragma unroll
    for (int t = 0; t < 4; t++) {
        int i = tid + t * 128;
        int r = i >> 2, kg = i & 3;
        int arow = bm + r;
        pA[t] = (arow < Mrows) ? 16 : 0;
        gA[t] = (size_t)(pA[t] ? arow : 0) * D_ + kg * 8;
        gW[t] = (size_t)(bn + r) * D_ + kg * 8;
        sO[t] = (uint32_t)(r * ASTRIDE + kg * 8) * 2;
    }

    const int li = lane & 7, ti = lane >> 3;
    int rowA[4], rowB[4];
#pragma unroll
    for (int mt = 0; mt < 4; mt++)
        rowA[mt] = (wm + mt * 16 + li + (ti & 1) * 8) * ASTRIDE + (ti >> 1) * 8;
#pragma unroll
    for (int np = 0; np < 4; np++)
        rowB[np] = (wn + np * 16 + li + (ti >> 1) * 8) * ASTRIDE + (ti & 1) * 8;

    float acc[4][8][4];
#pragma unroll
    for (int mt = 0; mt < 4; mt++)
#pragma unroll
        for (int nt = 0; nt < 8; nt++)
#pragma unroll
            for (int e = 0; e < 4; e++) acc[mt][nt][e] = 0.f;

    auto load_chunk = [&](int c) {
        const int kof = c * KC;
        const uint32_t st = smb + (c & 1) * STAGE_B;
#pragma unroll
        for (int t = 0; t < 4; t++) {
            cp16(st + 0 * ARR_B + sO[t], Xhi + gA[t] + kof, pA[t]);
            cp16(st + 1 * ARR_B + sO[t], Xlo + gA[t] + kof, pA[t]);
            cp16(st + 2 * ARR_B + sO[t], Whi + gW[t] + kof, 16);
            cp16(st + 3 * ARR_B + sO[t], Wlo + gW[t] + kof, 16);
        }
        CP_COMMIT();
    };

    load_chunk(0);

    const int NCH = D_ / KC;
    for (int c = 0; c < NCH; c++) {
        if (c + 1 < NCH) { load_chunk(c + 1); CP_WAIT1(); }
        else            { CP_WAIT0(); }
        __syncthreads();

        const uint32_t st = smb + (c & 1) * STAGE_B;
#pragma unroll
        for (int k16 = 0; k16 < KC; k16 += 16) {
            uint32_t ahi[4][4], alo[4][4];
#pragma unroll
            for (int mt = 0; mt < 4; mt++) {
                ldm4(ahi[mt][0], ahi[mt][1], ahi[mt][2], ahi[mt][3],
                     st + 0 * ARR_B + (uint32_t)(rowA[mt] + k16) * 2);
                ldm4(alo[mt][0], alo[mt][1], alo[mt][2], alo[mt][3],
                     st + 1 * ARR_B + (uint32_t)(rowA[mt] + k16) * 2);
            }
#pragma unroll
            for (int np = 0; np < 4; np++) {
                uint32_t bh0, bh1, bh2, bh3, bl0, bl1, bl2, bl3;
                ldm4(bh0, bh1, bh2, bh3, st + 2 * ARR_B + (uint32_t)(rowB[np] + k16) * 2);
                ldm4(bl0, bl1, bl2, bl3, st + 3 * ARR_B + (uint32_t)(rowB[np] + k16) * 2);
#pragma unroll
                for (int mt = 0; mt < 4; mt++) {
                    mma16816(acc[mt][2 * np + 0], ahi[mt], bh0, bh1);
                    mma16816(acc[mt][2 * np + 1], ahi[mt], bh2, bh3);
                    mma16816(acc[mt][2 * np + 0], ahi[mt], bl0, bl1);
                    mma16816(acc[mt][2 * np + 1], ahi[mt], bl2, bl3);
                    mma16816(acc[mt][2 * np + 0], alo[mt], bh0, bh1);
                    mma16816(acc[mt][2 * np + 1], alo[mt], bh2, bh3);
                }
            }
        }
        __syncthreads();
    }

    const int cg = lane >> 2, tg = lane & 3;

    if (mode == 0) {
#pragma unroll
        for (int mt = 0; mt < 4; mt++) {
            const int r0 = bm + wm + mt * 16 + cg;
            const int r1 = r0 + 8;
#pragma unroll
            for (int nt = 0; nt < 8; nt++) {
                const int col = bn + wn + nt * 8 + tg * 2;
                const float b0v = bq[col], b1v = bq[col + 1];
                if (r0 < Mrows) {
                    float2 o = make_float2(acc[mt][nt][0] + b0v, acc[mt][nt][1] + b1v);
                    *(float2*)(Y + (size_t)r0 * D_ + col) = o;
                }
                if (r1 < Mrows) {
                    float2 o = make_float2(acc[mt][nt][2] + b0v, acc[mt][nt][3] + b1v);
                    *(float2*)(Y + (size_t)r1 * D_ + col) = o;
                }
            }
        }
        return;
    }

    // ---- fused QKV epilogue: bias + (rope) + bf16 hi/lo split ----
    const int slab = bn >> 10;                       // 0=Q, 1=K, 2=V
    const int head = ((bn & 1023) + wn) >> 6;
    const float* bias = (slab == 0) ? bq : (slab == 1) ? bk : bv;
    __nv_bfloat16* Oh = (slab == 0) ? Qh : (slab == 1) ? Kh : Vh;
    __nv_bfloat16* Ol = (slab == 0) ? Ql : (slab == 1) ? Kl : Vl;
    const int npadX = (slab == 0) ? NPADQ : NPAD;
    const bool dorope = (slab < 2);

#pragma unroll
    for (int mt = 0; mt < 4; mt++) {
#pragma unroll
        for (int half = 0; half < 2; half++) {
            const int row = bm + wm + mt * 16 + cg + half * 8;
            if (row >= Mrows) continue;
            const int b = row / N_;
            const int n = row - b * N_;
            const size_t obase = ((size_t)(b * H_ + head) * npadX + n) * HD_;
            const int p = n - PREFIX_;
            const bool rp = dorope && (p >= 0);
            const int eb = half * 2;
#pragma unroll
            for (int nt = 0; nt < 4; nt++) {
                const int d = nt * 8 + 2 * tg;
                float x1a = acc[mt][nt][eb]     + bias[head * 64 + d];
                float x1b = acc[mt][nt][eb + 1] + bias[head * 64 + d + 1];
                float x2a = acc[mt][nt + 4][eb]     + bias[head * 64 + d + 32];
                float x2b = acc[mt][nt + 4][eb + 1] + bias[head * 64 + d + 33];
                float y1a = x1a, y1b = x1b, y2a = x2a, y2b = x2b;
                if (rp) {
                    const float* cp_ = cosp + p * HD_;
                    const float* sp_ = sinp + p * HD_;
                    float c1a = cp_[d], c1b = cp_[d + 1];
                    float c2a = cp_[d + 32], c2b = cp_[d + 33];
                    float s1a = sp_[d], s1b = sp_[d + 1];
                    float s2a = sp_[d + 32], s2b = sp_[d + 33];
                    y1a = x1a * c1a - x2a * s1a;  y2a = x2a * c2a + x1a * s2a;
                    y1b = x1b * c1b - x2b * s1b;  y2b = x2b * c2b + x1b * s2b;
                }
                float h1a = __bfloat162float(__float2bfloat16(y1a));
                float h1b = __bfloat162float(__float2bfloat16(y1b));
                float h2a = __bfloat162float(__float2bfloat16(y2a));
                float h2b = __bfloat162float(__float2bfloat16(y2b));
                *(uint32_t*)(Oh + obase + d)      = pack_bf16(h1a, h1b);
                *(uint32_t*)(Ol + obase + d)      = pack_bf16(y1a - h1a, y1b - h1b);
                *(uint32_t*)(Oh + obase + d + 32) = pack_bf16(h2a, h2b);
                *(uint32_t*)(Ol + obase + d + 32) = pack_bf16(y2a - h2a, y2b - h2b);
            }
        }
    }
}

// ------------- MMA flash attention: 128 q-rows per CTA, 8 warps ------------
#define ASTA   72
#define AARR   (64 * ASTA * 2)    // 9216 bytes (K/V arrays, 64 rows)
#define QARR   (128 * ASTA * 2)   // 18432 bytes (Q arrays, 128 rows)
#define ASMEM  (2 * QARR + 8 * AARR)  // 110592 bytes

__global__ __launch_bounds__(256)
void attn_mma_kernel(const __nv_bfloat16* __restrict__ Qh,
                     const __nv_bfloat16* __restrict__ Ql,
                     const __nv_bfloat16* __restrict__ Kh,
                     const __nv_bfloat16* __restrict__ Kl,
                     const __nv_bfloat16* __restrict__ Vh,
                     const __nv_bfloat16* __restrict__ Vl,
                     __nv_bfloat16* __restrict__ Ohi,
                     __nv_bfloat16* __restrict__ Olo) {
    extern __shared__ __align__(16) char asm_[];
    const uint32_t smb = smem_u32(asm_);
    const int tid = threadIdx.x, w = tid >> 5, lane = tid & 31;
    const int li = lane & 7, ti = lane >> 3;
    const int cg = lane >> 2, tg = lane & 3;
    const int bh = blockIdx.y;
    const int qt = blockIdx.x * 128;
    const int b = bh >> 4, h = bh & 15;

    const uint32_t QHS = smb, QLS = smb + QARR;
    const uint32_t KVB = smb + 2 * QARR;

    // ---- load Q tile (128 rows) ----
    {
        const size_t gq = ((size_t)bh * NPADQ + qt) * HD_;
        for (int c = tid; c < 1024; c += 256) {
            int r = c >> 3, k8 = c & 7;
            uint32_t off = (uint32_t)(r * ASTA + k8 * 8) * 2;
            cp16(QHS + off, Qh + gq + r * HD_ + k8 * 8, 16);
            cp16(QLS + off, Ql + gq + r * HD_ + k8 * 8, 16);
        }
        CP_COMMIT();
    }

    auto load_kv = [&](int t) {
        const uint32_t st = KVB + (t & 1) * 4 * AARR;
        const size_t gk = ((size_t)bh * NPAD + t * 64) * HD_;
        for (int c = tid; c < 512; c += 256) {
            int r = c >> 3, k8 = c & 7;
            uint32_t off = (uint32_t)(r * ASTA + k8 * 8) * 2;
            cp16(st + 0 * AARR + off, Kh + gk + r * HD_ + k8 * 8, 16);
            cp16(st + 1 * AARR + off, Kl + gk + r * HD_ + k8 * 8, 16);
            cp16(st + 2 * AARR + off, Vh + gk + r * HD_ + k8 * 8, 16);
            cp16(st + 3 * AARR + off, Vl + gk + r * HD_ + k8 * 8, 16);
        }
        CP_COMMIT();
    };

    load_kv(0);

    // ---- hoist Q fragments into registers (k-loop invariant) ----
    uint32_t qfh[4][4], qfl[4][4];
    {
        CP_WAIT1();           // Q group complete (kv0 may still be in flight)
        __syncthreads();
        const uint32_t aoff =
            (uint32_t)((16 * w + li + (ti & 1) * 8) * ASTA + (ti >> 1) * 8) * 2;
#pragma unroll
        for (int kk = 0; kk < 4; kk++) {
            ldm4(qfh[kk][0], qfh[kk][1], qfh[kk][2], qfh[kk][3], QHS + aoff + kk * 32);
            ldm4(qfl[kk][0], qfl[kk][1], qfl[kk][2], qfl[kk][3], QLS + aoff + kk * 32);
        }
    }

    float o[8][4];
#pragma unroll
    for (int nt = 0; nt < 8; nt++)
#pragma unroll
        for (int e = 0; e < 4; e++) o[nt][e] = 0.f;
    float m0 = -1e30f, m1 = -1e30f, l0 = 0.f, l1 = 0.f;

    uint32_t boff[4], voff[4];
#pragma unroll
    for (int np = 0; np < 4; np++) {
        boff[np] = (uint32_t)((np * 16 + li + (ti >> 1) * 8) * ASTA + (ti & 1) * 8) * 2;
        voff[np] = (uint32_t)(((ti & 1) * 8 + li) * ASTA + np * 16 + (ti >> 1) * 8) * 2;
    }

    const int NT = NPAD / 64;  // 17
    for (int t = 0; t < NT; t++) {
        if (t + 1 < NT) { load_kv(t + 1); CP_WAIT1(); }
        else            { CP_WAIT0(); }
        __syncthreads();
        const uint32_t st = KVB + (t & 1) * 4 * AARR;

        // ---- S = Q K^T (split 3x) ----
        float sacc[8][4];
#pragma unroll
        for (int nt = 0; nt < 8; nt++)
#pragma unroll
            for (int e = 0; e < 4; e++) sacc[nt][e] = 0.f;

#pragma unroll
        for (int kk = 0; kk < 4; kk++) {
#pragma unroll
            for (int np = 0; np < 4; np++) {
                uint32_t kh0, kh1, kh2, kh3, kl0, kl1, kl2, kl3;
                ldm4(kh0, kh1, kh2, kh3, st + 0 * AARR + boff[np] + kk * 32);
                ldm4(kl0, kl1, kl2, kl3, st + 1 * AARR + boff[np] + kk * 32);
                mma16816(sacc[2 * np + 0], qfh[kk], kh0, kh1);
                mma16816(sacc[2 * np + 1], qfh[kk], kh2, kh3);
                mma16816(sacc[2 * np + 0], qfh[kk], kl0, kl1);
                mma16816(sacc[2 * np + 1], qfh[kk], kl2, kl3);
                mma16816(sacc[2 * np + 0], qfl[kk], kh0, kh1);
                mma16816(sacc[2 * np + 1], qfl[kk], kh2, kh3);
            }
        }

        // ---- online softmax (masking only on the edge tile) ----
        float tm0 = -1e30f, tm1 = -1e30f;
        if (t != NT - 1) {
#pragma unroll
            for (int nt = 0; nt < 8; nt++) {
                float s0 = sacc[nt][0] * SCALE_, s1 = sacc[nt][1] * SCALE_;
                float s2 = sacc[nt][2] * SCALE_, s3 = sacc[nt][3] * SCALE_;
                sacc[nt][0] = s0; sacc[nt][1] = s1; sacc[nt][2] = s2; sacc[nt][3] = s3;
                tm0 = fmaxf(tm0, fmaxf(s0, s1));
                tm1 = fmaxf(tm1, fmaxf(s2, s3));
            }
        } else {
            const int colbase = t * 64 + 2 * tg;
#pragma unroll
            for (int nt = 0; nt < 8; nt++) {
                int c0 = colbase + nt * 8;
                float s0 = (c0     < N_) ? sacc[nt][0] * SCALE_ : -1e30f;
                float s1 = (c0 + 1 < N_) ? sacc[nt][1] * SCALE_ : -1e30f;
                float s2 = (c0     < N_) ? sacc[nt][2] * SCALE_ : -1e30f;
                float s3 = (c0 + 1 < N_) ? sacc[nt][3] * SCALE_ : -1e30f;
                sacc[nt][0] = s0; sacc[nt][1] = s1; sacc[nt][2] = s2; sacc[nt][3] = s3;
                tm0 = fmaxf(tm0, fmaxf(s0, s1));
                tm1 = fmaxf(tm1, fmaxf(s2, s3));
            }
        }
        tm0 = fmaxf(tm0, __shfl_xor_sync(0xffffffffu, tm0, 1));
        tm0 = fmaxf(tm0, __shfl_xor_sync(0xffffffffu, tm0, 2));
        tm1 = fmaxf(tm1, __shfl_xor_sync(0xffffffffu, tm1, 1));
        tm1 = fmaxf(tm1, __shfl_xor_sync(0xffffffffu, tm1, 2));
        float nm0 = fmaxf(m0, tm0), nm1 = fmaxf(m1, tm1);
        float cr0 = __expf(m0 - nm0), cr1 = __expf(m1 - nm1);
        m0 = nm0; m1 = nm1;

        uint32_t phf[4][4], plf[4][4];
        float rs0 = 0.f, rs1 = 0.f;
#pragma unroll
        for (int nt = 0; nt < 8; nt++) {
            float p0 = __expf(sacc[nt][0] - nm0);
            float p1 = __expf(sacc[nt][1] - nm0);
            float p2 = __expf(sacc[nt][2] - nm1);
            float p3 = __expf(sacc[nt][3] - nm1);
            rs0 += p0 + p1; rs1 += p2 + p3;
            float h0 = __bfloat162float(__float2bfloat16(p0));
            float h1 = __bfloat162float(__float2bfloat16(p1));
            float h2 = __bfloat162float(__float2bfloat16(p2));
            float h3 = __bfloat162float(__float2bfloat16(p3));
            uint32_t ph01 = pack_bf16(h0, h1);
            uint32_t ph23 = pack_bf16(h2, h3);
            uint32_t pl01 = pack_bf16(p0 - h0, p1 - h1);
            uint32_t pl23 = pack_bf16(p2 - h2, p3 - h3);
            int kk = nt >> 1;
            if ((nt & 1) == 0) {
                phf[kk][0] = ph01; phf[kk][1] = ph23;
                plf[kk][0] = pl01; plf[kk][1] = pl23;
            } else {
                phf[kk][2] = ph01; phf[kk][3] = ph23;
                plf[kk][2] = pl01; plf[kk][3] = pl23;
            }
        }
        rs0 += __shfl_xor_sync(0xffffffffu, rs0, 1);
        rs0 += __shfl_xor_sync(0xffffffffu, rs0, 2);
        rs1 += __shfl_xor_sync(0xffffffffu, rs1, 1);
        rs1 += __shfl_xor_sync(0xffffffffu, rs1, 2);
        l0 = l0 * cr0 + rs0;
        l1 = l1 * cr1 + rs1;
#pragma unroll
        for (int nt = 0; nt < 8; nt++) {
            o[nt][0] *= cr0; o[nt][1] *= cr0;
            o[nt][2] *= cr1; o[nt][3] *= cr1;
        }

        // ---- O += P V (split 3x, V via ldmatrix.trans) ----
#pragma unroll
        for (int kk = 0; kk < 4; kk++) {
            const uint32_t kadd = (uint32_t)(kk * 16 * ASTA) * 2;
#pragma unroll
            for (int np = 0; np < 4; np++) {
                uint32_t vh0, vh1, vh2, vh3, vl0, vl1, vl2, vl3;
                ldm4t(vh0, vh1, vh2, vh3, st + 2 * AARR + voff[np] + kadd);
                ldm4t(vl0, vl1, vl2, vl3, st + 3 * AARR + voff[np] + kadd);
                mma16816(o[2 * np + 0], phf[kk], vh0, vh1);
                mma16816(o[2 * np + 1], phf[kk], vh2, vh3);
                mma16816(o[2 * np + 0], phf[kk], vl0, vl1);
                mma16816(o[2 * np + 1], phf[kk], vl2, vl3);
                mma16816(o[2 * np + 0], plf[kk], vh0, vh1);
                mma16816(o[2 * np + 1], plf[kk], vh2, vh3);
            }
        }
        __syncthreads();
    }

    // ---- epilogue: normalize, split to bf16 hi/lo GEMM input ----
    const float inv0 = 1.f / l0, inv1 = 1.f / l1;
    const int r0 = qt + 16 * w + cg, r1 = r0 + 8;
#pragma unroll
    for (int nt = 0; nt < 8; nt++) {
        const int col = h * HD_ + nt * 8 + 2 * tg;
        if (r0 < N_) {
            float x0 = o[nt][0] * inv0, x1 = o[nt][1] * inv0;
            float h0 = __bfloat162float(__float2bfloat16(x0));
            float h1 = __bfloat162float(__float2bfloat16(x1));
            size_t dst = (size_t)(b * N_ + r0) * D_ + col;
            *(uint32_t*)(Ohi + dst) = pack_bf16(h0, h1);
            *(uint32_t*)(Olo + dst) = pack_bf16(x0 - h0, x1 - h1);
        }
        if (r1 < N_) {
            float x2 = o[nt][2] * inv1, x3 = o[nt][3] * inv1;
            float h2 = __bfloat162float(__float2bfloat16(x2));
            float h3 = __bfloat162float(__float2bfloat16(x3));
            size_t dst = (size_t)(b * N_ + r1) * D_ + col;
            *(uint32_t*)(Ohi + dst) = pack_bf16(h2, h3);
            *(uint32_t*)(Olo + dst) = pack_bf16(x2 - h2, x3 - h3);
        }
    }
}

// --------------------------------- launcher --------------------------------
extern "C" void kernel_launch(void* const* d_in, const int* in_sizes, int n_in,
                              void* d_out, int out_size) {
    const float* hs = (const float*)d_in[0];
    const float* sn = (const float*)d_in[1];
    const float* cs = (const float*)d_in[2];
    const float* Wq = (const float*)d_in[3];
    const float* bq = (const float*)d_in[4];
    const float* Wk = (const float*)d_in[5];
    const float* bk = (const float*)d_in[6];
    const float* Wv = (const float*)d_in[7];
    const float* bv = (const float*)d_in[8];
    const float* Wo = (const float*)d_in[9];
    const float* bo = (const float*)d_in[10];
    float* out = (float*)d_out;

    __nv_bfloat16 *Xhi, *Xlo, *Whi, *Wlo, *Qh, *Ql, *Kh, *Kl, *Vh, *Vl;
    cudaGetSymbolAddress((void**)&Xhi, g_Xhi);
    cudaGetSymbolAddress((void**)&Xlo, g_Xlo);
    cudaGetSymbolAddress((void**)&Whi, g_Whi);
    cudaGetSymbolAddress((void**)&Wlo, g_Wlo);
    cudaGetSymbolAddress((void**)&Qh,  g_Qh);
    cudaGetSymbolAddress((void**)&Ql,  g_Ql);
    cudaGetSymbolAddress((void**)&Kh,  g_Kh);
    cudaGetSymbolAddress((void**)&Kl,  g_Kl);
    cudaGetSymbolAddress((void**)&Vh,  g_Vh);
    cudaGetSymbolAddress((void**)&Vl,  g_Vl);

    cudaFuncSetAttribute(gemm_mma_kernel,
                         cudaFuncAttributeMaxDynamicSharedMemorySize, GSMEM);
    cudaFuncSetAttribute(attn_mma_kernel,
                         cudaFuncAttributeMaxDynamicSharedMemorySize, ASMEM);

    const int n4_hs = (M_TOT * D_) / 4;
    const int n4_w  = (D_ * D_) / 4;
    const size_t WN = (size_t)D_ * D_;

    dim3 cblk(256);
    dim3 cgrid_hs((n4_hs + 255) / 256);
    dim3 cgrid_w4((4 * n4_w + 255) / 256);
    dim3 qkvgrid(3 * D_ / 128, (M_TOT + 127) / 128), gblk(128);
    dim3 ogrid(D_ / 128, (M_TOT + 127) / 128);
    dim3 agrid(NPADQ / 128, B_ * H_), ablk(256);

    f32_split_kernel<<<cgrid_hs, cblk>>>(hs, Xhi, Xlo, n4_hs);
    w4_split_kernel<<<cgrid_w4, cblk>>>(Wq, Wk, Wv, Wo, Whi, Wlo, n4_w);

    // fused QKV projection + bias + rope + split (one launch, N=3072)
    gemm_mma_kernel<<<qkvgrid, gblk, GSMEM>>>(
        Xhi, Xlo, Whi, Wlo, bq, bk, bv, sn, cs,
        nullptr, Qh, Ql, Kh, Kl, Vh, Vl, M_TOT, 1);

    attn_mma_kernel<<<agrid, ablk, ASMEM>>>(Qh, Ql, Kh, Kl, Vh, Vl, Xhi, Xlo);

    // O projection
    gemm_mma_kernel<<<ogrid, gblk, GSMEM>>>(
        Xhi, Xlo, Whi + 3 * WN, Wlo + 3 * WN, bo, nullptr, nullptr, nullptr, nullptr,
        out, nullptr, nullptr, nullptr, nullptr, nullptr, nullptr, M_TOT, 0);
}